// round 11
// baseline (speedup 1.0000x reference)
#include <cuda_runtime.h>
#include <cuda_bf16.h>
#include <math.h>
#include <stdint.h>
#include <string.h>

#define HH   512
#define BB   256
#define SS   64
#define VV   32000
#define SB   (SS*BB)     // 16384
#define G4H  (4*HH)      // 2048
#define H2   (2*HH)      // 1024
#define G8H  (8*HH)      // 4096

// ------------------------- device scratch (no allocs) -------------------------
__device__ __align__(16) __nv_bfloat16 g_seq_hi[SB*HH],  g_seq_lo[SB*HH];
__device__ __align__(16) __nv_bfloat16 g_comb_hi[SB*H2], g_comb_lo[SB*H2];
__device__ __align__(16) float g_Xf[SB*G4H];
__device__ __align__(16) float g_Xb[SB*G4H];
__device__ __align__(16) float g_Xc[(size_t)SB*G8H];
__device__ __align__(16) __nv_bfloat16 g_Wihf_hi[G4H*HH], g_Wihf_lo[G4H*HH];
__device__ __align__(16) __nv_bfloat16 g_Whhf_hi[G4H*HH], g_Whhf_lo[G4H*HH];
__device__ __align__(16) __nv_bfloat16 g_Wihb_hi[G4H*HH], g_Wihb_lo[G4H*HH];
__device__ __align__(16) __nv_bfloat16 g_Whhb_hi[G4H*HH], g_Whhb_lo[G4H*HH];
__device__ __align__(16) __nv_bfloat16 g_Wihc_hi[G8H*H2], g_Wihc_lo[G8H*H2];
__device__ __align__(16) __nv_bfloat16 g_Whhc_hi[G8H*H2], g_Whhc_lo[G8H*H2];
__device__ __align__(16) __nv_bfloat16 g_Wout_hi[VV*H2],  g_Wout_lo[VV*H2];
__device__ __align__(16) float g_bfb[G4H], g_bbb[G4H], g_bcb[G8H];
// ping-pong recurrent h states, single-buffer c states
__device__ __align__(16) __nv_bfloat16 g_hf_hi[2][BB*HH], g_hf_lo[2][BB*HH];
__device__ __align__(16) __nv_bfloat16 g_hb_hi[2][BB*HH], g_hb_lo[2][BB*HH];
__device__ __align__(16) __nv_bfloat16 g_hc_hi[2][BB*H2], g_hc_lo[2][BB*H2];
__device__ __align__(16) float g_cf[BB*HH], g_cb[BB*HH], g_cc[BB*H2];
// software barrier counters
__device__ unsigned g_ctr_fb, g_ctr_c;

// ------------------------- helpers --------------------------------------------
__device__ __forceinline__ uint32_t s2u(const void* p){
    uint32_t a;
    asm("{ .reg .u64 t; cvta.to.shared.u64 t, %1; cvt.u32.u64 %0, t; }" : "=r"(a) : "l"(p));
    return a;
}
#define LDMX4(r, addr) \
    asm volatile("ldmatrix.sync.aligned.m8n8.x4.shared.b16 {%0,%1,%2,%3}, [%4];" \
        : "=r"((r)[0]), "=r"((r)[1]), "=r"((r)[2]), "=r"((r)[3]) : "r"(addr))
#define MMA16816(c, A, Bv) \
    asm volatile("mma.sync.aligned.m16n8k16.row.col.f32.bf16.bf16.f32 " \
        "{%0,%1,%2,%3}, {%4,%5,%6,%7}, {%8,%9}, {%0,%1,%2,%3};" \
        : "+f"((c)[0]), "+f"((c)[1]), "+f"((c)[2]), "+f"((c)[3]) \
        : "r"((A)[0]), "r"((A)[1]), "r"((A)[2]), "r"((A)[3]), "r"((Bv)[0]), "r"((Bv)[1]))
#define CPASYNC16(dst, src) \
    asm volatile("cp.async.cg.shared.global [%0], [%1], 16;" :: "r"(dst), "l"(src))
#define PREFETCH_L2(p) \
    asm volatile("prefetch.global.L2 [%0];" :: "l"(p))

// grid barrier (cooperative-groups pattern): release-red by leader, acquire poll
__device__ __forceinline__ void grid_barrier(unsigned* ctr, unsigned tgt, int tid){
    __syncthreads();
    if (tid == 0){
        asm volatile("red.release.gpu.global.add.u32 [%0], %1;" :: "l"(ctr), "r"(1u) : "memory");
        unsigned v;
        do {
            asm volatile("ld.acquire.gpu.global.u32 %0, [%1];" : "=r"(v) : "l"(ctr) : "memory");
            if (v < tgt) asm volatile("nanosleep.u32 128;");
        } while (v < tgt);
    }
    __syncthreads();
}

// ------------------------- plain HMMA GEMM kernel (512 threads) ----------------
// 128x128 tile, 16 warps (4/SMSP), warp sub-tile 32x32. blockIdx.z selects args.
struct GArgs {
    const __nv_bfloat16 *Ahi, *Alo;
    const __nv_bfloat16 *Bhi, *Blo;
    const float* bias;
    float* C;
    int ldc;
    int K;
};
struct GArgs2 { GArgs a[2]; };

#define RSB   144
#define TILEB (128*RSB)            // 18432
#define STGB  (4*TILEB)            // 73728
#define NSTG  3
#define SMEM_DYN (NSTG*STGB)       // 221184

__global__ __launch_bounds__(512, 1) void mma_gemm(GArgs2 P)
{
    const GArgs a = P.a[blockIdx.z];
    extern __shared__ char sm[];
    const int tid = threadIdx.x, lane = tid & 31, wid = tid >> 5;  // 0..15
    const int wm = wid & 3, wn = wid >> 2;     // 4 x 4 warp grid, 32x32 each
    const int m0 = blockIdx.y << 7;
    const int bx = blockIdx.x;
    const int K  = a.K;
    const int KB = K >> 6;

    auto issue = [&](int kb){
        char* sb = sm + (kb % NSTG) * STGB;
        const int k0 = kb << 6;
        #pragma unroll
        for (int i = 0; i < 8; i++){
            const int pos  = (i << 9) + tid;   // 0..4095 chunks
            const int tile = pos >> 10;
            const int rem  = pos & 1023;
            const int row  = rem >> 3;
            const int c8   = rem & 7;
            const __nv_bfloat16* src;
            if (tile == 0)      src = a.Ahi + (size_t)(m0 + row) * K + k0 + (c8 << 3);
            else if (tile == 1) src = a.Alo + (size_t)(m0 + row) * K + k0 + (c8 << 3);
            else src = (tile == 2 ? a.Bhi : a.Blo) + (size_t)((bx << 7) + row) * K + k0 + (c8 << 3);
            CPASYNC16(s2u(sb + tile * TILEB + row * RSB + (c8 << 4)), src);
        }
        asm volatile("cp.async.commit_group;" ::: "memory");
    };

    float acc[2][4][4];
    #pragma unroll
    for (int mt = 0; mt < 2; mt++)
        #pragma unroll
        for (int nt = 0; nt < 4; nt++)
            #pragma unroll
            for (int q = 0; q < 4; q++) acc[mt][nt][q] = 0.f;

    issue(0); issue(1);

    for (int kb = 0; kb < KB; kb++){
        if (kb + 2 < KB) issue(kb + 2);
        if (kb == KB - 1)      asm volatile("cp.async.wait_group 0;" ::: "memory");
        else if (kb == KB - 2) asm volatile("cp.async.wait_group 1;" ::: "memory");
        else                   asm volatile("cp.async.wait_group 2;" ::: "memory");
        __syncthreads();

        char* sb = sm + (kb % NSTG) * STGB;
        const uint32_t bAh = s2u(sb);
        const uint32_t bBh = bAh + 2 * TILEB;

        #pragma unroll
        for (int k16 = 0; k16 < 4; k16++){
            uint32_t Ah[2][4], Al[2][4], Bh[4][2], Bl[4][2];
            const int kcbA = (k16 << 5) + (((lane >> 4) & 1) << 4);
            #pragma unroll
            for (int mt = 0; mt < 2; mt++){
                const int row = (wm << 5) + (mt << 4) + (lane & 15);
                const uint32_t ad = bAh + row * RSB + kcbA;
                LDMX4(Ah[mt], ad);
                LDMX4(Al[mt], ad + TILEB);
            }
            {
                const int rowb = (wn << 5) + (((lane >> 4) & 1) << 3) + (lane & 7);
                const int kcbB = (k16 << 5) + (((lane >> 3) & 1) << 4);
                const uint32_t bd0 = bBh + rowb * RSB + kcbB;      // nt 0,1
                const uint32_t bd1 = bd0 + 16 * RSB;               // nt 2,3
                uint32_t t[4];
                LDMX4(t, bd0); Bh[0][0]=t[0]; Bh[0][1]=t[1]; Bh[1][0]=t[2]; Bh[1][1]=t[3];
                LDMX4(t, bd1); Bh[2][0]=t[0]; Bh[2][1]=t[1]; Bh[3][0]=t[2]; Bh[3][1]=t[3];
                LDMX4(t, bd0 + TILEB); Bl[0][0]=t[0]; Bl[0][1]=t[1]; Bl[1][0]=t[2]; Bl[1][1]=t[3];
                LDMX4(t, bd1 + TILEB); Bl[2][0]=t[0]; Bl[2][1]=t[1]; Bl[3][0]=t[2]; Bl[3][1]=t[3];
            }
            #pragma unroll
            for (int mt = 0; mt < 2; mt++)
                #pragma unroll
                for (int nt = 0; nt < 4; nt++){
                    MMA16816(acc[mt][nt], Ah[mt], Bh[nt]);
                    MMA16816(acc[mt][nt], Ah[mt], Bl[nt]);
                    MMA16816(acc[mt][nt], Al[mt], Bh[nt]);
                }
        }
        __syncthreads();
    }

    const int g = lane >> 2, tig = lane & 3;
    #pragma unroll
    for (int mt = 0; mt < 2; mt++){
        const int r = m0 + (wm << 5) + (mt << 4) + g;
        #pragma unroll
        for (int nt = 0; nt < 4; nt++){
            const int n = (bx << 7) + (wn << 5) + (nt << 3) + (tig << 1);
            const float b0 = a.bias[n], b1 = a.bias[n + 1];
            float* c0p = a.C + (size_t)r * a.ldc + n;
            float* c1p = a.C + (size_t)(r + 8) * a.ldc + n;
            c0p[0] = acc[mt][nt][0] + b0; c0p[1] = acc[mt][nt][1] + b1;
            c1p[0] = acc[mt][nt][2] + b0; c1p[1] = acc[mt][nt][3] + b1;
        }
    }
}

// ==================== persistent fwd+bwd recurrence kernel =====================
// 128 CTAs x 512 threads (16 warps, 4/SMSP). cell=bid&1, mhalf=(bid>>1)&1, jg=bid>>2.
#define W_TERM  73728
#define FB_WKB  9216
#define FB_AST  36864
#define FB_ATRM 18432
#define ABASE   147456

__global__ __launch_bounds__(512, 1) void lstm_fb()
{
    extern __shared__ char sm[];
    const int tid = threadIdx.x, lane = tid & 31, wid = tid >> 5;  // wid 0..15
    const int bid = blockIdx.x;
    const int cell = bid & 1, mhalf = (bid >> 1) & 1, jg = bid >> 2;
    const int wm = wid & 3, wn = wid >> 2;   // wm: 32-row group, wn: 16-col group

    {
        const __nv_bfloat16* Whi = cell ? g_Whhb_hi : g_Whhf_hi;
        const __nv_bfloat16* Wlo = cell ? g_Whhb_lo : g_Whhf_lo;
        #pragma unroll
        for (int i = 0; i < 16; i++){
            const int q = (i << 9) + tid;        // 0..8191
            const int term = q >> 12;
            const int rem  = q & 4095;
            const int row  = rem >> 6;
            const int c    = rem & 63;
            const int wrow = (row & 3) * HH + (jg << 4) + (row >> 2);
            const __nv_bfloat16* src = (term ? Wlo : Whi) + (size_t)wrow * HH + (c << 3);
            CPASYNC16(s2u(sm + term * W_TERM + (c >> 3) * FB_WKB + row * 144 + ((c & 7) << 4)), src);
        }
        asm volatile("cp.async.commit_group;" ::: "memory");
        asm volatile("cp.async.wait_group 0;" ::: "memory");
        __syncthreads();
    }

    const uint32_t wbase = s2u(sm);
    char* abase = sm + ABASE;
    float* cst = cell ? g_cb : g_cf;
    const int g = lane >> 2, tig = lane & 3;
    const bool odd = (tig & 1);

    for (int s = 0; s < SS; s++){
        const int rb = s & 1, wb = rb ^ 1;
        const __nv_bfloat16* Ahi = cell ? g_hb_hi[rb] : g_hf_hi[rb];
        const __nv_bfloat16* Alo = cell ? g_hb_lo[rb] : g_hf_lo[rb];
        const float* Xp = cell ? (g_Xb + (size_t)(SS - 1 - s) * BB * G4H)
                               : (g_Xf + (size_t)s * BB * G4H);

        if (tid < 256){
            const float* pf = Xp + (size_t)((mhalf << 7) + (tid >> 1)) * G4H
                              + ((tid & 1) << 1) * HH + (jg << 4);
            PREFETCH_L2(pf);
            PREFETCH_L2(pf + HH);
        }

        auto issueA = [&](int kb){
            char* sb = abase + (kb & 1) * FB_AST;
            const int k0 = kb << 6;
            #pragma unroll
            for (int i = 0; i < 4; i++){
                const int q = (i << 9) + tid;    // 0..2047
                const int term = q >> 10;
                const int rem  = q & 1023;
                const int row  = rem >> 3;
                const int c8   = rem & 7;
                const __nv_bfloat16* src = (term ? Alo : Ahi)
                    + (size_t)((mhalf << 7) + row) * HH + k0 + (c8 << 3);
                CPASYNC16(s2u(sb + term * FB_ATRM + row * 144 + (c8 << 4)), src);
            }
            asm volatile("cp.async.commit_group;" ::: "memory");
        };

        float acc[2][2][4];
        #pragma unroll
        for (int mt = 0; mt < 2; mt++)
            #pragma unroll
            for (int nt = 0; nt < 2; nt++)
                #pragma unroll
                for (int q = 0; q < 4; q++) acc[mt][nt][q] = 0.f;

        issueA(0);
        for (int kb = 0; kb < 8; kb++){
            if (kb + 1 < 8){ issueA(kb + 1); asm volatile("cp.async.wait_group 1;" ::: "memory"); }
            else            asm volatile("cp.async.wait_group 0;" ::: "memory");
            __syncthreads();
            const uint32_t sa = s2u(abase + (kb & 1) * FB_AST);
            #pragma unroll
            for (int k16 = 0; k16 < 4; k16++){
                uint32_t Ah[2][4], Al[2][4], Bh[2][2], Bl[2][2];
                const int kcbA = (k16 << 5) + (((lane >> 4) & 1) << 4);
                #pragma unroll
                for (int mt = 0; mt < 2; mt++){
                    const int row = (wm << 5) + (mt << 4) + (lane & 15);
                    const uint32_t ad = sa + row * 144 + kcbA;
                    LDMX4(Ah[mt], ad);
                    LDMX4(Al[mt], ad + FB_ATRM);
                }
                {
                    const int rowb = (wn << 4) + (((lane >> 4) & 1) << 3) + (lane & 7);
                    const int kcbB = (k16 << 5) + (((lane >> 3) & 1) << 4);
                    const uint32_t bw = wbase + kb * FB_WKB + rowb * 144 + kcbB;
                    uint32_t t[4];
                    LDMX4(t, bw);          Bh[0][0]=t[0]; Bh[0][1]=t[1]; Bh[1][0]=t[2]; Bh[1][1]=t[3];
                    LDMX4(t, bw + W_TERM); Bl[0][0]=t[0]; Bl[0][1]=t[1]; Bl[1][0]=t[2]; Bl[1][1]=t[3];
                }
                #pragma unroll
                for (int mt = 0; mt < 2; mt++)
                    #pragma unroll
                    for (int nt = 0; nt < 2; nt++){
                        MMA16816(acc[mt][nt], Ah[mt], Bh[nt]);
                        MMA16816(acc[mt][nt], Ah[mt], Bl[nt]);
                        MMA16816(acc[mt][nt], Al[mt], Bh[nt]);
                    }
            }
            __syncthreads();
        }

        __nv_bfloat16* Hhi = cell ? g_hb_hi[wb] : g_hf_hi[wb];
        __nv_bfloat16* Hlo = cell ? g_hb_lo[wb] : g_hf_lo[wb];
        #pragma unroll
        for (int mt = 0; mt < 2; mt++)
            #pragma unroll
            for (int nt = 0; nt < 2; nt++){
                float c0 = acc[mt][nt][0], c1 = acc[mt][nt][1];
                float c2 = acc[mt][nt][2], c3 = acc[mt][nt][3];
                float e0 = __shfl_xor_sync(0xFFFFFFFFu, odd ? c0 : c2, 1);
                float e1 = __shfl_xor_sync(0xFFFFFFFFu, odd ? c1 : c3, 1);
                const int r = (mhalf << 7) + (wm << 5) + (mt << 4) + g + (odd ? 8 : 0);
                const int j = (jg << 4) + (wn << 2) + (nt << 1) + (tig >> 1);
                float gi, gf, gg, go;
                if (odd){ gi = e0; gf = e1; gg = c2; go = c3; }
                else    { gi = c0; gf = c1; gg = e0; go = e1; }
                const float* Xrow = Xp + (size_t)r * G4H;
                gi += Xrow[j]; gf += Xrow[HH + j]; gg += Xrow[2*HH + j]; go += Xrow[3*HH + j];
                const float ii = 1.f / (1.f + expf(-gi));
                const float ff = 1.f / (1.f + expf(-gf));
                const float gt = tanhf(gg);
                const float oo = 1.f / (1.f + expf(-go));
                const size_t si = (size_t)r * HH + j;
                const float cn = ff * cst[si] + ii * gt;
                const float hn = oo * tanhf(cn);
                cst[si] = cn;
                const __nv_bfloat16 hh = __float2bfloat16(hn);
                const __nv_bfloat16 hl = __float2bfloat16(hn - __bfloat162float(hh));
                Hhi[si] = hh; Hlo[si] = hl;
                const size_t ci = (size_t)(s * BB + r) * H2 + cell * HH + j;
                g_comb_hi[ci] = hh; g_comb_lo[ci] = hl;
            }

        grid_barrier(&g_ctr_fb, 128u * (unsigned)(s + 1), tid);
    }
}

// ==================== persistent combiner recurrence kernel ====================
#define CW_TERM 65536
#define CW_KB   2048
#define CA_BASE 131072
#define CA_ST   32768
#define CA_TERM 16384
#define COMB_SMEM (CA_BASE + 2*CA_ST)   // 196608

__device__ __forceinline__ uint32_t csw(int row, int c){
    return (uint32_t)(row * 64 + ((c ^ ((row >> 1) & 3)) << 4));
}

__global__ __launch_bounds__(512, 1) void lstm_comb()
{
    extern __shared__ char sm[];
    const int tid = threadIdx.x, lane = tid & 31, wid = tid >> 5;  // wid 0..15
    const int jg = blockIdx.x;
    const int wm = wid & 7, wn = wid >> 3;

    {
        #pragma unroll
        for (int i = 0; i < 16; i++){
            const int q = (i << 9) + tid;        // 0..8191
            const int term = q >> 12;
            const int rem  = q & 4095;
            const int row  = rem >> 7;
            const int cc   = rem & 127;
            const int kb   = cc >> 2;
            const int c    = cc & 3;
            const int wrow = (row & 3) * H2 + (jg << 3) + (row >> 2);
            const __nv_bfloat16* src = (term ? g_Whhc_lo : g_Whhc_hi) + (size_t)wrow * H2 + (cc << 3);
            CPASYNC16(s2u(sm + term * CW_TERM + kb * CW_KB + csw(row, c)), src);
        }
        asm volatile("cp.async.commit_group;" ::: "memory");
        asm volatile("cp.async.wait_group 0;" ::: "memory");
        __syncthreads();
    }

    const uint32_t wbase = s2u(sm);
    char* abase = sm + CA_BASE;
    const int g = lane >> 2, tig = lane & 3;
    const bool odd = (tig & 1);

    for (int s = 0; s < SS; s++){
        const int rb = s & 1, wb = rb ^ 1;
        const __nv_bfloat16* Ahi = g_hc_hi[rb];
        const __nv_bfloat16* Alo = g_hc_lo[rb];
        const float* Xp = g_Xc + (size_t)s * BB * G8H;

        if (tid < 256){
            const float* pf = Xp + (size_t)tid * G8H + (jg << 3);
            PREFETCH_L2(pf);
            PREFETCH_L2(pf + H2);
            PREFETCH_L2(pf + 2 * H2);
            PREFETCH_L2(pf + 3 * H2);
        }

        auto issueA = [&](int kb){
            char* sb = abase + (kb & 1) * CA_ST;
            const int k0 = kb << 5;
            #pragma unroll
            for (int i = 0; i < 4; i++){
                const int q = (i << 9) + tid;    // 0..2047
                const int term = q >> 10;
                const int rem  = q & 1023;
                const int row  = rem >> 2;
                const int c    = rem & 3;
                const __nv_bfloat16* src = (term ? Alo : Ahi) + (size_t)row * H2 + k0 + (c << 3);
                CPASYNC16(s2u(sb + term * CA_TERM + csw(row, c)), src);
            }
            asm volatile("cp.async.commit_group;" ::: "memory");
        };

        float acc[2][2][4];
        #pragma unroll
        for (int mt = 0; mt < 2; mt++)
            #pragma unroll
            for (int nt = 0; nt < 2; nt++)
                #pragma unroll
                for (int q = 0; q < 4; q++) acc[mt][nt][q] = 0.f;

        issueA(0);
        for (int kb = 0; kb < 32; kb++){
            if (kb + 1 < 32){ issueA(kb + 1); asm volatile("cp.async.wait_group 1;" ::: "memory"); }
            else             asm volatile("cp.async.wait_group 0;" ::: "memory");
            __syncthreads();
            const uint32_t sa = s2u(abase + (kb & 1) * CA_ST);
            #pragma unroll
            for (int k16 = 0; k16 < 2; k16++){
                uint32_t Ah[2][4], Al[2][4], Bh[2][2], Bl[2][2];
                const int cA = (k16 << 1) + ((lane >> 4) & 1);
                #pragma unroll
                for (int mt = 0; mt < 2; mt++){
                    const int row = (wm << 5) + (mt << 4) + (lane & 15);
                    const uint32_t ad = sa + csw(row, cA);
                    LDMX4(Ah[mt], ad);
                    LDMX4(Al[mt], ad + CA_TERM);
                }
                {
                    const int rowb = (wn << 4) + (((lane >> 4) & 1) << 3) + (lane & 7);
                    const int cB = (k16 << 1) + ((lane >> 3) & 1);
                    const uint32_t bw = wbase + kb * CW_KB + csw(rowb, cB);
                    uint32_t t[4];
                    LDMX4(t, bw);           Bh[0][0]=t[0]; Bh[0][1]=t[1]; Bh[1][0]=t[2]; Bh[1][1]=t[3];
                    LDMX4(t, bw + CW_TERM); Bl[0][0]=t[0]; Bl[0][1]=t[1]; Bl[1][0]=t[2]; Bl[1][1]=t[3];
                }
                #pragma unroll
                for (int mt = 0; mt < 2; mt++)
                    #pragma unroll
                    for (int nt = 0; nt < 2; nt++){
                        MMA16816(acc[mt][nt], Ah[mt], Bh[nt]);
                        MMA16816(acc[mt][nt], Ah[mt], Bl[nt]);
                        MMA16816(acc[mt][nt], Al[mt], Bh[nt]);
                    }
            }
            __syncthreads();
        }

        #pragma unroll
        for (int mt = 0; mt < 2; mt++)
            #pragma unroll
            for (int nt = 0; nt < 2; nt++){
                float c0 = acc[mt][nt][0], c1 = acc[mt][nt][1];
                float c2 = acc[mt][nt][2], c3 = acc[mt][nt][3];
                float e0 = __shfl_xor_sync(0xFFFFFFFFu, odd ? c0 : c2, 1);
                float e1 = __shfl_xor_sync(0xFFFFFFFFu, odd ? c1 : c3, 1);
                const int r = (wm << 5) + (mt << 4) + g + (odd ? 8 : 0);
                const int j = (jg << 3) + (wn << 2) + (nt << 1) + (tig >> 1);
                float gi, gf, gg, go;
                if (odd){ gi = e0; gf = e1; gg = c2; go = c3; }
                else    { gi = c0; gf = c1; gg = e0; go = e1; }
                const float* Xrow = Xp + (size_t)r * G8H;
                gi += Xrow[j]; gf += Xrow[H2 + j]; gg += Xrow[2*H2 + j]; go += Xrow[3*H2 + j];
                const float ii = 1.f / (1.f + expf(-gi));
                const float ff = 1.f / (1.f + expf(-gf));
                const float gt = tanhf(gg);
                const float oo = 1.f / (1.f + expf(-go));
                const size_t si = (size_t)r * H2 + j;
                const float cn = ff * g_cc[si] + ii * gt;
                const float hn = oo * tanhf(cn);
                g_cc[si] = cn;
                const __nv_bfloat16 hh = __float2bfloat16(hn);
                const __nv_bfloat16 hl = __float2bfloat16(hn - __bfloat162float(hh));
                g_hc_hi[wb][si] = hh; g_hc_lo[wb][si] = hl;
            }

        grid_barrier(&g_ctr_c, 128u * (unsigned)(s + 1), tid);
    }
}

// ------------------------- fused prep kernel -----------------------------------
__device__ __forceinline__ void split1(const float* __restrict__ src,
                                       __nv_bfloat16* __restrict__ hi,
                                       __nv_bfloat16* __restrict__ lo, long i){
    float v = src[i];
    __nv_bfloat16 h = __float2bfloat16(v);
    hi[i] = h;
    lo[i] = __float2bfloat16(v - __bfloat162float(h));
}

#define SZ_FB  (G4H*HH)
#define SZ_C   (G8H*H2)
#define SZ_OUT ((long)VV*H2)
#define OFF_SPLITS (4L*SZ_FB + 2L*SZ_C + SZ_OUT)
#define OFF_EMB    (OFF_SPLITS + (long)SB*HH)
#define OFF_ST1    (OFF_EMB + (long)BB*HH)
#define OFF_ST2    (OFF_ST1 + (long)BB*H2)
#define OFF_END    (OFF_ST2 + G4H + G4H + G8H)

__global__ void prep_all(const int* __restrict__ x, const float* __restrict__ Wemb,
                         const float* Wih_f, const float* Whh_f, const float* bih_f, const float* bhh_f,
                         const float* Wih_b, const float* Whh_b, const float* bih_b, const float* bhh_b,
                         const float* Wih_c, const float* Whh_c, const float* bih_c, const float* bhh_c,
                         const float* Wout,
                         const float* h0f, const float* c0f, const float* h0b, const float* c0b,
                         const float* h0c, const float* c0c)
{
    const long stride = (long)gridDim.x * blockDim.x;
    for (long i = (long)blockIdx.x * blockDim.x + threadIdx.x; i < OFF_END; i += stride){
        if (i == 0){ g_ctr_fb = 0; g_ctr_c = 0; }
        if (i < OFF_SPLITS){
            long r = i;
            if (r < SZ_FB){ split1(Wih_f, g_Wihf_hi, g_Wihf_lo, r); continue; } r -= SZ_FB;
            if (r < SZ_FB){ split1(Whh_f, g_Whhf_hi, g_Whhf_lo, r); continue; } r -= SZ_FB;
            if (r < SZ_FB){ split1(Wih_b, g_Wihb_hi, g_Wihb_lo, r); continue; } r -= SZ_FB;
            if (r < SZ_FB){ split1(Whh_b, g_Whhb_hi, g_Whhb_lo, r); continue; } r -= SZ_FB;
            if (r < SZ_C){ split1(Wih_c, g_Wihc_hi, g_Wihc_lo, r); continue; } r -= SZ_C;
            if (r < SZ_C){ split1(Whh_c, g_Whhc_hi, g_Whhc_lo, r); continue; } r -= SZ_C;
            split1(Wout, g_Wout_hi, g_Wout_lo, r);
        } else if (i < OFF_EMB){
            long e = i - OFF_SPLITS;
            int row = (int)(e >> 9), k = (int)(e & 511);
            int tok = x[row];
            float v = tok ? Wemb[(size_t)tok * HH + k] : 0.f;
            __nv_bfloat16 h = __float2bfloat16(v);
            g_seq_hi[e] = h;
            g_seq_lo[e] = __float2bfloat16(v - __bfloat162float(h));
        } else if (i < OFF_ST1){
            long t = i - OFF_EMB;
            float vf = h0f[t]; __nv_bfloat16 hf = __float2bfloat16(vf);
            g_hf_hi[0][t] = hf; g_hf_lo[0][t] = __float2bfloat16(vf - __bfloat162float(hf));
            g_cf[t] = c0f[t];
            float vb = h0b[t]; __nv_bfloat16 hb = __float2bfloat16(vb);
            g_hb_hi[0][t] = hb; g_hb_lo[0][t] = __float2bfloat16(vb - __bfloat162float(hb));
            g_cb[t] = c0b[t];
        } else if (i < OFF_ST2){
            long t = i - OFF_ST1;
            float vc = h0c[t]; __nv_bfloat16 hc = __float2bfloat16(vc);
            g_hc_hi[0][t] = hc; g_hc_lo[0][t] = __float2bfloat16(vc - __bfloat162float(hc));
            g_cc[t] = c0c[t];
        } else {
            long b = i - OFF_ST2;
            if (b < G4H) g_bfb[b] = bih_f[b] + bhh_f[b];
            else if (b < 2*G4H) g_bbb[b - G4H] = bih_b[b - G4H] + bhh_b[b - G4H];
            else g_bcb[b - 2*G4H] = bih_c[b - 2*G4H] + bhh_c[b - 2*G4H];
        }
    }
}

// ------------------------- host orchestration ---------------------------------
static void* sym(const void* s){ void* p; cudaGetSymbolAddress(&p, s); return p; }

extern "C" void kernel_launch(void* const* d_in, const int* in_sizes, int n_in,
                              void* d_out, int out_size) {
    (void)in_sizes; (void)n_in; (void)out_size;

    const int*   x     = (const int*)  d_in[0];
    const float* Wemb  = (const float*)d_in[1];
    const float* Wih_f = (const float*)d_in[2];
    const float* Whh_f = (const float*)d_in[3];
    const float* bih_f = (const float*)d_in[4];
    const float* bhh_f = (const float*)d_in[5];
    const float* Wih_b = (const float*)d_in[6];
    const float* Whh_b = (const float*)d_in[7];
    const float* bih_b = (const float*)d_in[8];
    const float* bhh_b = (const float*)d_in[9];
    const float* Wih_c = (const float*)d_in[10];
    const float* Whh_c = (const float*)d_in[11];
    const float* bih_c = (const float*)d_in[12];
    const float* bhh_c = (const float*)d_in[13];
    const float* Wout  = (const float*)d_in[14];
    const float* bout  = (const float*)d_in[15];
    const float* h0f   = (const float*)d_in[16];
    const float* c0f   = (const float*)d_in[17];
    const float* h0b   = (const float*)d_in[18];
    const float* c0b   = (const float*)d_in[19];
    const float* h0c   = (const float*)d_in[20];
    const float* c0c   = (const float*)d_in[21];
    float* out = (float*)d_out;

    cudaFuncSetAttribute(mma_gemm,  cudaFuncAttributeMaxDynamicSharedMemorySize, SMEM_DYN);
    cudaFuncSetAttribute(lstm_fb,   cudaFuncAttributeMaxDynamicSharedMemorySize, SMEM_DYN);
    cudaFuncSetAttribute(lstm_comb, cudaFuncAttributeMaxDynamicSharedMemorySize, COMB_SMEM);

    __nv_bfloat16 *seq_hi = (__nv_bfloat16*)sym(g_seq_hi), *seq_lo = (__nv_bfloat16*)sym(g_seq_lo);
    __nv_bfloat16 *cmb_hi = (__nv_bfloat16*)sym(g_comb_hi), *cmb_lo = (__nv_bfloat16*)sym(g_comb_lo);
    float *Xf = (float*)sym(g_Xf), *Xb = (float*)sym(g_Xb), *Xc = (float*)sym(g_Xc);
    __nv_bfloat16 *Wihf_hi=(__nv_bfloat16*)sym(g_Wihf_hi), *Wihf_lo=(__nv_bfloat16*)sym(g_Wihf_lo);
    __nv_bfloat16 *Wihb_hi=(__nv_bfloat16*)sym(g_Wihb_hi), *Wihb_lo=(__nv_bfloat16*)sym(g_Wihb_lo);
    __nv_bfloat16 *Wihc_hi=(__nv_bfloat16*)sym(g_Wihc_hi), *Wihc_lo=(__nv_bfloat16*)sym(g_Wihc_lo);
    __nv_bfloat16 *Wout_hi=(__nv_bfloat16*)sym(g_Wout_hi), *Wout_lo=(__nv_bfloat16*)sym(g_Wout_lo);
    float *bfb=(float*)sym(g_bfb), *bbb=(float*)sym(g_bbb), *bcb=(float*)sym(g_bcb);
    __nv_bfloat16 *hc_hi=(__nv_bfloat16*)sym(g_hc_hi), *hc_lo=(__nv_bfloat16*)sym(g_hc_lo);

    // launch 0: fused prep
    prep_all<<<4096, 256>>>(x, Wemb,
                            Wih_f, Whh_f, bih_f, bhh_f,
                            Wih_b, Whh_b, bih_b, bhh_b,
                            Wih_c, Whh_c, bih_c, bhh_c,
                            Wout, h0f, c0f, h0b, c0b, h0c, c0c);

    GArgs2 P; GArgs z; memset(&z, 0, sizeof(z));

    // launch 1: Xf + Xb merged (z selects)
    P.a[0]=z; P.a[0].Ahi=seq_hi; P.a[0].Alo=seq_lo; P.a[0].Bhi=Wihf_hi; P.a[0].Blo=Wihf_lo;
    P.a[0].bias=bfb; P.a[0].C=Xf; P.a[0].ldc=G4H; P.a[0].K=HH;
    P.a[1]=P.a[0]; P.a[1].Bhi=Wihb_hi; P.a[1].Blo=Wihb_lo; P.a[1].bias=bbb; P.a[1].C=Xb;
    mma_gemm<<<dim3(G4H/128, SB/128, 2), 512, SMEM_DYN>>>(P);

    // launch 2: persistent fwd+bwd recurrence
    lstm_fb<<<128, 512, SMEM_DYN>>>();

    // launch 3: Xc
    P.a[0]=z; P.a[0].Ahi=cmb_hi; P.a[0].Alo=cmb_lo; P.a[0].Bhi=Wihc_hi; P.a[0].Blo=Wihc_lo;
    P.a[0].bias=bcb; P.a[0].C=Xc; P.a[0].ldc=G8H; P.a[0].K=H2; P.a[1]=P.a[0];
    mma_gemm<<<dim3(G8H/128, SB/128, 1), 512, SMEM_DYN>>>(P);

    // launch 4: persistent combiner recurrence
    lstm_comb<<<128, 512, COMB_SMEM>>>();

    // launch 5: head
    P.a[0]=z; P.a[0].Ahi=hc_hi; P.a[0].Alo=hc_lo; P.a[0].Bhi=Wout_hi; P.a[0].Blo=Wout_lo;
    P.a[0].bias=bout; P.a[0].C=out; P.a[0].ldc=VV; P.a[0].K=H2; P.a[1]=P.a[0];
    mma_gemm<<<dim3(VV/128, BB/128, 1), 512, SMEM_DYN>>>(P);
}

// round 12
// speedup vs baseline: 1.3995x; 1.3995x over previous
#include <cuda_runtime.h>
#include <cuda_fp16.h>
#include <math.h>
#include <stdint.h>
#include <string.h>

#define HH   512
#define BB   256
#define SS   64
#define VV   32000
#define SB   (SS*BB)     // 16384
#define G4H  (4*HH)      // 2048
#define H2   (2*HH)      // 1024
#define G8H  (8*HH)      // 4096

#define WSCALE 1024.0f
#define INVS   (1.0f/1024.0f)

// ------------------------- device scratch (no allocs) -------------------------
__device__ __align__(16) __half g_seq [SB*HH];            // activations: 1 fp16 word
__device__ __align__(16) __half g_comb[SB*H2];
__device__ __align__(16) float g_Xf[SB*G4H];
__device__ __align__(16) float g_Xb[SB*G4H];
__device__ __align__(16) float g_Xc[(size_t)SB*G8H];
// weights: scaled (x1024) fp16 hi+lo pairs
__device__ __align__(16) __half g_Wihf_hi[G4H*HH], g_Wihf_lo[G4H*HH];
__device__ __align__(16) __half g_Whhf_hi[G4H*HH], g_Whhf_lo[G4H*HH];
__device__ __align__(16) __half g_Wihb_hi[G4H*HH], g_Wihb_lo[G4H*HH];
__device__ __align__(16) __half g_Whhb_hi[G4H*HH], g_Whhb_lo[G4H*HH];
__device__ __align__(16) __half g_Wihc_hi[G8H*H2], g_Wihc_lo[G8H*H2];
__device__ __align__(16) __half g_Whhc_hi[G8H*H2], g_Whhc_lo[G8H*H2];
__device__ __align__(16) __half g_Wout_hi[VV*H2],  g_Wout_lo[VV*H2];
__device__ __align__(16) float g_bfb[G4H], g_bbb[G4H], g_bcb[G8H];
// recurrent states: h single fp16 (ping-pong); hc keeps a lo residual for the head
__device__ __align__(16) __half g_hf[2][BB*HH];
__device__ __align__(16) __half g_hb[2][BB*HH];
__device__ __align__(16) __half g_hc_hi[2][BB*H2], g_hc_lo[2][BB*H2];
__device__ __align__(16) float g_cf[BB*HH], g_cb[BB*HH], g_cc[BB*H2];
__device__ unsigned g_ctr_fb, g_ctr_c;

// ------------------------- helpers --------------------------------------------
__device__ __forceinline__ uint32_t s2u(const void* p){
    uint32_t a;
    asm("{ .reg .u64 t; cvta.to.shared.u64 t, %1; cvt.u32.u64 %0, t; }" : "=r"(a) : "l"(p));
    return a;
}
#define LDMX4(r, addr) \
    asm volatile("ldmatrix.sync.aligned.m8n8.x4.shared.b16 {%0,%1,%2,%3}, [%4];" \
        : "=r"((r)[0]), "=r"((r)[1]), "=r"((r)[2]), "=r"((r)[3]) : "r"(addr))
#define MMA16816(c, A, Bv) \
    asm volatile("mma.sync.aligned.m16n8k16.row.col.f32.f16.f16.f32 " \
        "{%0,%1,%2,%3}, {%4,%5,%6,%7}, {%8,%9}, {%0,%1,%2,%3};" \
        : "+f"((c)[0]), "+f"((c)[1]), "+f"((c)[2]), "+f"((c)[3]) \
        : "r"((A)[0]), "r"((A)[1]), "r"((A)[2]), "r"((A)[3]), "r"((Bv)[0]), "r"((Bv)[1]))
#define CPASYNC16(dst, src) \
    asm volatile("cp.async.cg.shared.global [%0], [%1], 16;" :: "r"(dst), "l"(src))
#define PREFETCH_L2(p) \
    asm volatile("prefetch.global.L2 [%0];" :: "l"(p))

__device__ __forceinline__ void grid_barrier(unsigned* ctr, unsigned tgt, int tid){
    __syncthreads();
    if (tid == 0){
        asm volatile("red.release.gpu.global.add.u32 [%0], %1;" :: "l"(ctr), "r"(1u) : "memory");
        unsigned v;
        do {
            asm volatile("ld.acquire.gpu.global.u32 %0, [%1];" : "=r"(v) : "l"(ctr) : "memory");
            if (v < tgt) asm volatile("nanosleep.u32 128;");
        } while (v < tgt);
    }
    __syncthreads();
}

// ------------------------- HMMA GEMM kernel (512 threads) ----------------------
// AT=1: C = (Ah·(Bh+Bl))*INVS + bias   (2 MMAs per frag pair)
// AT=2: C = ((Ah+Al)·approx)*INVS+bias (3 MMAs: AhBh+AhBl+AlBh) -- head
struct GArgs {
    const __half *Ahi, *Alo;
    const __half *Bhi, *Blo;
    const float* bias;
    float* C;
    int ldc;
    int K;
};
struct GArgs2 { GArgs a[2]; };

#define RSB   144
#define TILEB (128*RSB)            // 18432
#define STGB  (4*TILEB)            // 73728 (tile1 unused when AT=1)
#define NSTG  3
#define SMEM_DYN (NSTG*STGB)       // 221184

template<int AT>
__global__ __launch_bounds__(512, 1) void mma_gemm(GArgs2 P)
{
    const GArgs a = P.a[blockIdx.z];
    extern __shared__ char sm[];
    const int tid = threadIdx.x, lane = tid & 31, wid = tid >> 5;
    const int wm = wid & 3, wn = wid >> 2;     // 4x4 warp grid, 32x32 each
    const int m0 = blockIdx.y << 7;
    const int bx = blockIdx.x;
    const int K  = a.K;
    const int KB = K >> 6;

    auto issue = [&](int kb){
        char* sb = sm + (kb % NSTG) * STGB;
        const int k0 = kb << 6;
        const int NI = (AT == 2) ? 8 : 6;
        #pragma unroll
        for (int i = 0; i < NI; i++){
            int tile;
            if (AT == 2) tile = i >> 1;
            else { const int ts = i >> 1; tile = (ts == 0) ? 0 : ts + 1; }  // {0,2,3}
            const int rem  = ((i & 1) << 9) + tid;   // 0..1023
            const int row  = rem >> 3;
            const int c8   = rem & 7;
            const __half* src;
            if (tile == 0)      src = a.Ahi + (size_t)(m0 + row) * K + k0 + (c8 << 3);
            else if (tile == 1) src = a.Alo + (size_t)(m0 + row) * K + k0 + (c8 << 3);
            else src = (tile == 2 ? a.Bhi : a.Blo) + (size_t)((bx << 7) + row) * K + k0 + (c8 << 3);
            CPASYNC16(s2u(sb + tile * TILEB + row * RSB + (c8 << 4)), src);
        }
        asm volatile("cp.async.commit_group;" ::: "memory");
    };

    float acc[2][4][4];
    #pragma unroll
    for (int mt = 0; mt < 2; mt++)
        #pragma unroll
        for (int nt = 0; nt < 4; nt++)
            #pragma unroll
            for (int q = 0; q < 4; q++) acc[mt][nt][q] = 0.f;

    issue(0); issue(1);

    for (int kb = 0; kb < KB; kb++){
        if (kb + 2 < KB) issue(kb + 2);
        if (kb == KB - 1)      asm volatile("cp.async.wait_group 0;" ::: "memory");
        else if (kb == KB - 2) asm volatile("cp.async.wait_group 1;" ::: "memory");
        else                   asm volatile("cp.async.wait_group 2;" ::: "memory");
        __syncthreads();

        char* sb = sm + (kb % NSTG) * STGB;
        const uint32_t bAh = s2u(sb);
        const uint32_t bBh = bAh + 2 * TILEB;

        #pragma unroll
        for (int k16 = 0; k16 < 4; k16++){
            uint32_t Ah[2][4], Al[2][4], Bh[4][2], Bl[4][2];
            const int kcbA = (k16 << 5) + (((lane >> 4) & 1) << 4);
            #pragma unroll
            for (int mt = 0; mt < 2; mt++){
                const int row = (wm << 5) + (mt << 4) + (lane & 15);
                const uint32_t ad = bAh + row * RSB + kcbA;
                LDMX4(Ah[mt], ad);
                if (AT == 2) LDMX4(Al[mt], ad + TILEB);
            }
            {
                const int rowb = (wn << 5) + (((lane >> 4) & 1) << 3) + (lane & 7);
                const int kcbB = (k16 << 5) + (((lane >> 3) & 1) << 4);
                const uint32_t bd0 = bBh + rowb * RSB + kcbB;
                const uint32_t bd1 = bd0 + 16 * RSB;
                uint32_t t[4];
                LDMX4(t, bd0); Bh[0][0]=t[0]; Bh[0][1]=t[1]; Bh[1][0]=t[2]; Bh[1][1]=t[3];
                LDMX4(t, bd1); Bh[2][0]=t[0]; Bh[2][1]=t[1]; Bh[3][0]=t[2]; Bh[3][1]=t[3];
                LDMX4(t, bd0 + TILEB); Bl[0][0]=t[0]; Bl[0][1]=t[1]; Bl[1][0]=t[2]; Bl[1][1]=t[3];
                LDMX4(t, bd1 + TILEB); Bl[2][0]=t[0]; Bl[2][1]=t[1]; Bl[3][0]=t[2]; Bl[3][1]=t[3];
            }
            #pragma unroll
            for (int mt = 0; mt < 2; mt++)
                #pragma unroll
                for (int nt = 0; nt < 4; nt++){
                    MMA16816(acc[mt][nt], Ah[mt], Bh[nt]);
                    MMA16816(acc[mt][nt], Ah[mt], Bl[nt]);
                    if (AT == 2) MMA16816(acc[mt][nt], Al[mt], Bh[nt]);
                }
        }
        __syncthreads();
    }

    const int g = lane >> 2, tig = lane & 3;
    #pragma unroll
    for (int mt = 0; mt < 2; mt++){
        const int r = m0 + (wm << 5) + (mt << 4) + g;
        #pragma unroll
        for (int nt = 0; nt < 4; nt++){
            const int n = (bx << 7) + (wn << 5) + (nt << 3) + (tig << 1);
            const float b0 = a.bias[n], b1 = a.bias[n + 1];
            float* c0p = a.C + (size_t)r * a.ldc + n;
            float* c1p = a.C + (size_t)(r + 8) * a.ldc + n;
            c0p[0] = acc[mt][nt][0] * INVS + b0; c0p[1] = acc[mt][nt][1] * INVS + b1;
            c1p[0] = acc[mt][nt][2] * INVS + b0; c1p[1] = acc[mt][nt][3] * INVS + b1;
        }
    }
}

// ==================== persistent fwd+bwd recurrence kernel =====================
// 128 CTAs x 512 threads. Weights (scaled hi+lo) resident; A (h) single fp16.
#define W_TERM  73728
#define FB_WKB  9216
#define FB_AST  18432
#define ABASE   147456
#define FB_SMEM (ABASE + 2*FB_AST)   // 184320

__global__ __launch_bounds__(512, 1) void lstm_fb()
{
    extern __shared__ char sm[];
    const int tid = threadIdx.x, lane = tid & 31, wid = tid >> 5;
    const int bid = blockIdx.x;
    const int cell = bid & 1, mhalf = (bid >> 1) & 1, jg = bid >> 2;
    const int wm = wid & 3, wn = wid >> 2;

    {
        const __half* Whi = cell ? g_Whhb_hi : g_Whhf_hi;
        const __half* Wlo = cell ? g_Whhb_lo : g_Whhf_lo;
        #pragma unroll
        for (int i = 0; i < 16; i++){
            const int q = (i << 9) + tid;        // 0..8191
            const int term = q >> 12;
            const int rem  = q & 4095;
            const int row  = rem >> 6;
            const int c    = rem & 63;
            const int wrow = (row & 3) * HH + (jg << 4) + (row >> 2);
            const __half* src = (term ? Wlo : Whi) + (size_t)wrow * HH + (c << 3);
            CPASYNC16(s2u(sm + term * W_TERM + (c >> 3) * FB_WKB + row * 144 + ((c & 7) << 4)), src);
        }
        asm volatile("cp.async.commit_group;" ::: "memory");
        asm volatile("cp.async.wait_group 0;" ::: "memory");
        __syncthreads();
    }

    const uint32_t wbase = s2u(sm);
    char* abase = sm + ABASE;
    float* cst = cell ? g_cb : g_cf;
    const int g = lane >> 2, tig = lane & 3;
    const bool odd = (tig & 1);

    for (int s = 0; s < SS; s++){
        const int rb = s & 1, wb = rb ^ 1;
        const __half* Ain = cell ? g_hb[rb] : g_hf[rb];
        const float* Xp = cell ? (g_Xb + (size_t)(SS - 1 - s) * BB * G4H)
                               : (g_Xf + (size_t)s * BB * G4H);

        if (tid < 256){
            const float* pf = Xp + (size_t)((mhalf << 7) + (tid >> 1)) * G4H
                              + ((tid & 1) << 1) * HH + (jg << 4);
            PREFETCH_L2(pf);
            PREFETCH_L2(pf + HH);
        }

        auto issueA = [&](int kb){
            char* sb = abase + (kb & 1) * FB_AST;
            const int k0 = kb << 6;
            #pragma unroll
            for (int i = 0; i < 2; i++){
                const int rem = (i << 9) + tid;  // 0..1023
                const int row = rem >> 3;
                const int c8  = rem & 7;
                const __half* src = Ain + (size_t)((mhalf << 7) + row) * HH + k0 + (c8 << 3);
                CPASYNC16(s2u(sb + row * 144 + (c8 << 4)), src);
            }
            asm volatile("cp.async.commit_group;" ::: "memory");
        };

        float acc[2][2][4];
        #pragma unroll
        for (int mt = 0; mt < 2; mt++)
            #pragma unroll
            for (int nt = 0; nt < 2; nt++)
                #pragma unroll
                for (int q = 0; q < 4; q++) acc[mt][nt][q] = 0.f;

        issueA(0);
        for (int kb = 0; kb < 8; kb++){
            if (kb + 1 < 8){ issueA(kb + 1); asm volatile("cp.async.wait_group 1;" ::: "memory"); }
            else            asm volatile("cp.async.wait_group 0;" ::: "memory");
            __syncthreads();
            const uint32_t sa = s2u(abase + (kb & 1) * FB_AST);
            #pragma unroll
            for (int k16 = 0; k16 < 4; k16++){
                uint32_t Ah[2][4], Bh[2][2], Bl[2][2];
                const int kcbA = (k16 << 5) + (((lane >> 4) & 1) << 4);
                #pragma unroll
                for (int mt = 0; mt < 2; mt++){
                    const int row = (wm << 5) + (mt << 4) + (lane & 15);
                    LDMX4(Ah[mt], sa + row * 144 + kcbA);
                }
                {
                    const int rowb = (wn << 4) + (((lane >> 4) & 1) << 3) + (lane & 7);
                    const int kcbB = (k16 << 5) + (((lane >> 3) & 1) << 4);
                    const uint32_t bw = wbase + kb * FB_WKB + rowb * 144 + kcbB;
                    uint32_t t[4];
                    LDMX4(t, bw);          Bh[0][0]=t[0]; Bh[0][1]=t[1]; Bh[1][0]=t[2]; Bh[1][1]=t[3];
                    LDMX4(t, bw + W_TERM); Bl[0][0]=t[0]; Bl[0][1]=t[1]; Bl[1][0]=t[2]; Bl[1][1]=t[3];
                }
                #pragma unroll
                for (int mt = 0; mt < 2; mt++)
                    #pragma unroll
                    for (int nt = 0; nt < 2; nt++){
                        MMA16816(acc[mt][nt], Ah[mt], Bh[nt]);
                        MMA16816(acc[mt][nt], Ah[mt], Bl[nt]);
                    }
            }
            __syncthreads();
        }

        __half* Hout = cell ? g_hb[wb] : g_hf[wb];
        #pragma unroll
        for (int mt = 0; mt < 2; mt++)
            #pragma unroll
            for (int nt = 0; nt < 2; nt++){
                float c0 = acc[mt][nt][0], c1 = acc[mt][nt][1];
                float c2 = acc[mt][nt][2], c3 = acc[mt][nt][3];
                float e0 = __shfl_xor_sync(0xFFFFFFFFu, odd ? c0 : c2, 1);
                float e1 = __shfl_xor_sync(0xFFFFFFFFu, odd ? c1 : c3, 1);
                const int r = (mhalf << 7) + (wm << 5) + (mt << 4) + g + (odd ? 8 : 0);
                const int j = (jg << 4) + (wn << 2) + (nt << 1) + (tig >> 1);
                float gi, gf, gg, go;
                if (odd){ gi = e0; gf = e1; gg = c2; go = c3; }
                else    { gi = c0; gf = c1; gg = e0; go = e1; }
                const float* Xrow = Xp + (size_t)r * G4H;
                gi = gi * INVS + Xrow[j];
                gf = gf * INVS + Xrow[HH + j];
                gg = gg * INVS + Xrow[2*HH + j];
                go = go * INVS + Xrow[3*HH + j];
                const float ii = 1.f / (1.f + expf(-gi));
                const float ff = 1.f / (1.f + expf(-gf));
                const float gt = tanhf(gg);
                const float oo = 1.f / (1.f + expf(-go));
                const size_t si = (size_t)r * HH + j;
                const float cn = ff * cst[si] + ii * gt;
                const float hn = oo * tanhf(cn);
                cst[si] = cn;
                const __half hh = __float2half(hn);
                Hout[si] = hh;
                g_comb[(size_t)(s * BB + r) * H2 + cell * HH + j] = hh;
            }

        grid_barrier(&g_ctr_fb, 128u * (unsigned)(s + 1), tid);
    }
}

// ==================== persistent combiner recurrence kernel ====================
#define CW_TERM 65536
#define CW_KB   2048
#define CA_BASE 131072
#define CA_ST   16384
#define COMB_SMEM (CA_BASE + 2*CA_ST)   // 163840

__device__ __forceinline__ uint32_t csw(int row, int c){
    return (uint32_t)(row * 64 + ((c ^ ((row >> 1) & 3)) << 4));
}

__global__ __launch_bounds__(512, 1) void lstm_comb()
{
    extern __shared__ char sm[];
    const int tid = threadIdx.x, lane = tid & 31, wid = tid >> 5;
    const int jg = blockIdx.x;
    const int wm = wid & 7, wn = wid >> 3;

    {
        #pragma unroll
        for (int i = 0; i < 16; i++){
            const int q = (i << 9) + tid;        // 0..8191
            const int term = q >> 12;
            const int rem  = q & 4095;
            const int row  = rem >> 7;
            const int cc   = rem & 127;
            const int kb   = cc >> 2;
            const int c    = cc & 3;
            const int wrow = (row & 3) * H2 + (jg << 3) + (row >> 2);
            const __half* src = (term ? g_Whhc_lo : g_Whhc_hi) + (size_t)wrow * H2 + (cc << 3);
            CPASYNC16(s2u(sm + term * CW_TERM + kb * CW_KB + csw(row, c)), src);
        }
        asm volatile("cp.async.commit_group;" ::: "memory");
        asm volatile("cp.async.wait_group 0;" ::: "memory");
        __syncthreads();
    }

    const uint32_t wbase = s2u(sm);
    char* abase = sm + CA_BASE;
    const int g = lane >> 2, tig = lane & 3;
    const bool odd = (tig & 1);

    for (int s = 0; s < SS; s++){
        const int rb = s & 1, wb = rb ^ 1;
        const __half* Ain = g_hc_hi[rb];
        const float* Xp = g_Xc + (size_t)s * BB * G8H;

        if (tid < 256){
            const float* pf = Xp + (size_t)tid * G8H + (jg << 3);
            PREFETCH_L2(pf);
            PREFETCH_L2(pf + H2);
            PREFETCH_L2(pf + 2 * H2);
            PREFETCH_L2(pf + 3 * H2);
        }

        auto issueA = [&](int kb){
            char* sb = abase + (kb & 1) * CA_ST;
            const int k0 = kb << 5;
            #pragma unroll
            for (int i = 0; i < 2; i++){
                const int rem = (i << 9) + tid;  // 0..1023
                const int row = rem >> 2;
                const int c   = rem & 3;
                const __half* src = Ain + (size_t)row * H2 + k0 + (c << 3);
                CPASYNC16(s2u(sb + csw(row, c)), src);
            }
            asm volatile("cp.async.commit_group;" ::: "memory");
        };

        float acc[2][2][4];
        #pragma unroll
        for (int mt = 0; mt < 2; mt++)
            #pragma unroll
            for (int nt = 0; nt < 2; nt++)
                #pragma unroll
                for (int q = 0; q < 4; q++) acc[mt][nt][q] = 0.f;

        issueA(0);
        for (int kb = 0; kb < 32; kb++){
            if (kb + 1 < 32){ issueA(kb + 1); asm volatile("cp.async.wait_group 1;" ::: "memory"); }
            else             asm volatile("cp.async.wait_group 0;" ::: "memory");
            __syncthreads();
            const uint32_t sa = s2u(abase + (kb & 1) * CA_ST);
            #pragma unroll
            for (int k16 = 0; k16 < 2; k16++){
                uint32_t Ah[2][4], Bh[2][2], Bl[2][2];
                const int cA = (k16 << 1) + ((lane >> 4) & 1);
                #pragma unroll
                for (int mt = 0; mt < 2; mt++){
                    const int row = (wm << 5) + (mt << 4) + (lane & 15);
                    LDMX4(Ah[mt], sa + csw(row, cA));
                }
                {
                    const int rowb = (wn << 4) + (((lane >> 4) & 1) << 3) + (lane & 7);
                    const int cB = (k16 << 1) + ((lane >> 3) & 1);
                    const uint32_t bw = wbase + kb * CW_KB + csw(rowb, cB);
                    uint32_t t[4];
                    LDMX4(t, bw);           Bh[0][0]=t[0]; Bh[0][1]=t[1]; Bh[1][0]=t[2]; Bh[1][1]=t[3];
                    LDMX4(t, bw + CW_TERM); Bl[0][0]=t[0]; Bl[0][1]=t[1]; Bl[1][0]=t[2]; Bl[1][1]=t[3];
                }
                #pragma unroll
                for (int mt = 0; mt < 2; mt++)
                    #pragma unroll
                    for (int nt = 0; nt < 2; nt++){
                        MMA16816(acc[mt][nt], Ah[mt], Bh[nt]);
                        MMA16816(acc[mt][nt], Ah[mt], Bl[nt]);
                    }
            }
            __syncthreads();
        }

        #pragma unroll
        for (int mt = 0; mt < 2; mt++)
            #pragma unroll
            for (int nt = 0; nt < 2; nt++){
                float c0 = acc[mt][nt][0], c1 = acc[mt][nt][1];
                float c2 = acc[mt][nt][2], c3 = acc[mt][nt][3];
                float e0 = __shfl_xor_sync(0xFFFFFFFFu, odd ? c0 : c2, 1);
                float e1 = __shfl_xor_sync(0xFFFFFFFFu, odd ? c1 : c3, 1);
                const int r = (wm << 5) + (mt << 4) + g + (odd ? 8 : 0);
                const int j = (jg << 3) + (wn << 2) + (nt << 1) + (tig >> 1);
                float gi, gf, gg, go;
                if (odd){ gi = e0; gf = e1; gg = c2; go = c3; }
                else    { gi = c0; gf = c1; gg = e0; go = e1; }
                const float* Xrow = Xp + (size_t)r * G8H;
                gi = gi * INVS + Xrow[j];
                gf = gf * INVS + Xrow[H2 + j];
                gg = gg * INVS + Xrow[2*H2 + j];
                go = go * INVS + Xrow[3*H2 + j];
                const float ii = 1.f / (1.f + expf(-gi));
                const float ff = 1.f / (1.f + expf(-gf));
                const float gt = tanhf(gg);
                const float oo = 1.f / (1.f + expf(-go));
                const size_t si = (size_t)r * H2 + j;
                const float cn = ff * g_cc[si] + ii * gt;
                const float hn = oo * tanhf(cn);
                g_cc[si] = cn;
                const __half hh = __float2half(hn);
                g_hc_hi[wb][si] = hh;
                g_hc_lo[wb][si] = __float2half(hn - __half2float(hh));
            }

        grid_barrier(&g_ctr_c, 128u * (unsigned)(s + 1), tid);
    }
}

// ------------------------- fused prep kernel -----------------------------------
__device__ __forceinline__ void splitw(const float* __restrict__ src,
                                       __half* __restrict__ hi,
                                       __half* __restrict__ lo, long i){
    float v = src[i] * WSCALE;               // exact pow-2 scale
    __half h = __float2half(v);
    hi[i] = h;
    lo[i] = __float2half(v - __half2float(h));
}

#define SZ_FB  (G4H*HH)
#define SZ_C   (G8H*H2)
#define SZ_OUT ((long)VV*H2)
#define OFF_SPLITS (4L*SZ_FB + 2L*SZ_C + SZ_OUT)
#define OFF_EMB    (OFF_SPLITS + (long)SB*HH)
#define OFF_ST1    (OFF_EMB + (long)BB*HH)
#define OFF_ST2    (OFF_ST1 + (long)BB*H2)
#define OFF_END    (OFF_ST2 + G4H + G4H + G8H)

__global__ void prep_all(const int* __restrict__ x, const float* __restrict__ Wemb,
                         const float* Wih_f, const float* Whh_f, const float* bih_f, const float* bhh_f,
                         const float* Wih_b, const float* Whh_b, const float* bih_b, const float* bhh_b,
                         const float* Wih_c, const float* Whh_c, const float* bih_c, const float* bhh_c,
                         const float* Wout,
                         const float* h0f, const float* c0f, const float* h0b, const float* c0b,
                         const float* h0c, const float* c0c)
{
    const long stride = (long)gridDim.x * blockDim.x;
    for (long i = (long)blockIdx.x * blockDim.x + threadIdx.x; i < OFF_END; i += stride){
        if (i == 0){ g_ctr_fb = 0; g_ctr_c = 0; }
        if (i < OFF_SPLITS){
            long r = i;
            if (r < SZ_FB){ splitw(Wih_f, g_Wihf_hi, g_Wihf_lo, r); continue; } r -= SZ_FB;
            if (r < SZ_FB){ splitw(Whh_f, g_Whhf_hi, g_Whhf_lo, r); continue; } r -= SZ_FB;
            if (r < SZ_FB){ splitw(Wih_b, g_Wihb_hi, g_Wihb_lo, r); continue; } r -= SZ_FB;
            if (r < SZ_FB){ splitw(Whh_b, g_Whhb_hi, g_Whhb_lo, r); continue; } r -= SZ_FB;
            if (r < SZ_C){ splitw(Wih_c, g_Wihc_hi, g_Wihc_lo, r); continue; } r -= SZ_C;
            if (r < SZ_C){ splitw(Whh_c, g_Whhc_hi, g_Whhc_lo, r); continue; } r -= SZ_C;
            splitw(Wout, g_Wout_hi, g_Wout_lo, r);
        } else if (i < OFF_EMB){
            long e = i - OFF_SPLITS;
            int row = (int)(e >> 9), k = (int)(e & 511);
            int tok = x[row];
            float v = tok ? Wemb[(size_t)tok * HH + k] : 0.f;
            g_seq[e] = __float2half(v);
        } else if (i < OFF_ST1){
            long t = i - OFF_EMB;
            g_hf[0][t] = __float2half(h0f[t]); g_cf[t] = c0f[t];
            g_hb[0][t] = __float2half(h0b[t]); g_cb[t] = c0b[t];
        } else if (i < OFF_ST2){
            long t = i - OFF_ST1;
            float vc = h0c[t];
            __half hh = __float2half(vc);
            g_hc_hi[0][t] = hh;
            g_hc_lo[0][t] = __float2half(vc - __half2float(hh));
            g_cc[t] = c0c[t];
        } else {
            long b = i - OFF_ST2;
            if (b < G4H) g_bfb[b] = bih_f[b] + bhh_f[b];
            else if (b < 2*G4H) g_bbb[b - G4H] = bih_b[b - G4H] + bhh_b[b - G4H];
            else g_bcb[b - 2*G4H] = bih_c[b - 2*G4H] + bhh_c[b - 2*G4H];
        }
    }
}

// ------------------------- host orchestration ---------------------------------
static void* sym(const void* s){ void* p; cudaGetSymbolAddress(&p, s); return p; }

extern "C" void kernel_launch(void* const* d_in, const int* in_sizes, int n_in,
                              void* d_out, int out_size) {
    (void)in_sizes; (void)n_in; (void)out_size;

    const int*   x     = (const int*)  d_in[0];
    const float* Wemb  = (const float*)d_in[1];
    const float* Wih_f = (const float*)d_in[2];
    const float* Whh_f = (const float*)d_in[3];
    const float* bih_f = (const float*)d_in[4];
    const float* bhh_f = (const float*)d_in[5];
    const float* Wih_b = (const float*)d_in[6];
    const float* Whh_b = (const float*)d_in[7];
    const float* bih_b = (const float*)d_in[8];
    const float* bhh_b = (const float*)d_in[9];
    const float* Wih_c = (const float*)d_in[10];
    const float* Whh_c = (const float*)d_in[11];
    const float* bih_c = (const float*)d_in[12];
    const float* bhh_c = (const float*)d_in[13];
    const float* Wout  = (const float*)d_in[14];
    const float* bout  = (const float*)d_in[15];
    const float* h0f   = (const float*)d_in[16];
    const float* c0f   = (const float*)d_in[17];
    const float* h0b   = (const float*)d_in[18];
    const float* c0b   = (const float*)d_in[19];
    const float* h0c   = (const float*)d_in[20];
    const float* c0c   = (const float*)d_in[21];
    float* out = (float*)d_out;

    cudaFuncSetAttribute(mma_gemm<1>, cudaFuncAttributeMaxDynamicSharedMemorySize, SMEM_DYN);
    cudaFuncSetAttribute(mma_gemm<2>, cudaFuncAttributeMaxDynamicSharedMemorySize, SMEM_DYN);
    cudaFuncSetAttribute(lstm_fb,     cudaFuncAttributeMaxDynamicSharedMemorySize, FB_SMEM);
    cudaFuncSetAttribute(lstm_comb,   cudaFuncAttributeMaxDynamicSharedMemorySize, COMB_SMEM);

    __half *seq = (__half*)sym(g_seq), *cmb = (__half*)sym(g_comb);
    float *Xf = (float*)sym(g_Xf), *Xb = (float*)sym(g_Xb), *Xc = (float*)sym(g_Xc);
    __half *Wihf_hi=(__half*)sym(g_Wihf_hi), *Wihf_lo=(__half*)sym(g_Wihf_lo);
    __half *Wihb_hi=(__half*)sym(g_Wihb_hi), *Wihb_lo=(__half*)sym(g_Wihb_lo);
    __half *Wihc_hi=(__half*)sym(g_Wihc_hi), *Wihc_lo=(__half*)sym(g_Wihc_lo);
    __half *Wout_hi=(__half*)sym(g_Wout_hi), *Wout_lo=(__half*)sym(g_Wout_lo);
    float *bfb=(float*)sym(g_bfb), *bbb=(float*)sym(g_bbb), *bcb=(float*)sym(g_bcb);
    __half *hc_hi=(__half*)sym(g_hc_hi), *hc_lo=(__half*)sym(g_hc_lo);

    // launch 0: fused prep
    prep_all<<<4096, 256>>>(x, Wemb,
                            Wih_f, Whh_f, bih_f, bhh_f,
                            Wih_b, Whh_b, bih_b, bhh_b,
                            Wih_c, Whh_c, bih_c, bhh_c,
                            Wout, h0f, c0f, h0b, c0b, h0c, c0c);

    GArgs2 P; GArgs z; memset(&z, 0, sizeof(z));

    // launch 1: Xf + Xb (AT=1)
    P.a[0]=z; P.a[0].Ahi=seq; P.a[0].Alo=seq; P.a[0].Bhi=Wihf_hi; P.a[0].Blo=Wihf_lo;
    P.a[0].bias=bfb; P.a[0].C=Xf; P.a[0].ldc=G4H; P.a[0].K=HH;
    P.a[1]=P.a[0]; P.a[1].Bhi=Wihb_hi; P.a[1].Blo=Wihb_lo; P.a[1].bias=bbb; P.a[1].C=Xb;
    mma_gemm<1><<<dim3(G4H/128, SB/128, 2), 512, SMEM_DYN>>>(P);

    // launch 2: persistent fwd+bwd recurrence
    lstm_fb<<<128, 512, FB_SMEM>>>();

    // launch 3: Xc (AT=1)
    P.a[0]=z; P.a[0].Ahi=cmb; P.a[0].Alo=cmb; P.a[0].Bhi=Wihc_hi; P.a[0].Blo=Wihc_lo;
    P.a[0].bias=bcb; P.a[0].C=Xc; P.a[0].ldc=G8H; P.a[0].K=H2; P.a[1]=P.a[0];
    mma_gemm<1><<<dim3(G8H/128, SB/128, 1), 512, SMEM_DYN>>>(P);

    // launch 4: persistent combiner recurrence
    lstm_comb<<<128, 512, COMB_SMEM>>>();

    // launch 5: head (AT=2, hc split hi/lo for full precision on the output path)
    P.a[0]=z; P.a[0].Ahi=hc_hi; P.a[0].Alo=hc_lo; P.a[0].Bhi=Wout_hi; P.a[0].Blo=Wout_lo;
    P.a[0].bias=bout; P.a[0].C=out; P.a[0].ldc=VV; P.a[0].K=H2; P.a[1]=P.a[0];
    mma_gemm<2><<<dim3(VV/128, BB/128, 1), 512, SMEM_DYN>>>(P);
}

// round 13
// speedup vs baseline: 1.5578x; 1.1131x over previous
#include <cuda_runtime.h>
#include <cuda_fp16.h>
#include <math.h>
#include <stdint.h>
#include <string.h>

#define HH   512
#define BB   256
#define SS   64
#define VV   32000
#define SB   (SS*BB)     // 16384
#define G4H  (4*HH)      // 2048
#define H2   (2*HH)      // 1024
#define G8H  (8*HH)      // 4096

#define WSCALE 1024.0f
#define INVS   (1.0f/1024.0f)

// ------------------------- device scratch (no allocs) -------------------------
__device__ __align__(16) __half g_seq [SB*HH];
__device__ __align__(16) __half g_comb[SB*H2];
__device__ __align__(16) float g_Xf[SB*G4H];
__device__ __align__(16) float g_Xb[SB*G4H];
__device__ __align__(16) float g_Xc[(size_t)SB*G8H];
// weights: scaled (x1024) fp16. ih/out: hi+lo pairs; hh (recurrence): hi only used.
__device__ __align__(16) __half g_Wihf_hi[G4H*HH], g_Wihf_lo[G4H*HH];
__device__ __align__(16) __half g_Whhf_hi[G4H*HH];
__device__ __align__(16) __half g_Wihb_hi[G4H*HH], g_Wihb_lo[G4H*HH];
__device__ __align__(16) __half g_Whhb_hi[G4H*HH];
__device__ __align__(16) __half g_Wihc_hi[G8H*H2], g_Wihc_lo[G8H*H2];
__device__ __align__(16) __half g_Whhc_hi[G8H*H2];
__device__ __align__(16) __half g_Wout_hi[VV*H2],  g_Wout_lo[VV*H2];
__device__ __align__(16) float g_bfb[G4H], g_bbb[G4H], g_bcb[G8H];
// recurrent states
__device__ __align__(16) __half g_hf[2][BB*HH];
__device__ __align__(16) __half g_hb[2][BB*HH];
__device__ __align__(16) __half g_hc_hi[2][BB*H2], g_hc_lo[2][BB*H2];
__device__ __align__(16) float g_cf[BB*HH], g_cb[BB*HH], g_cc[BB*H2];
__device__ unsigned g_ctr_fb, g_ctr_c;

// ------------------------- helpers --------------------------------------------
__device__ __forceinline__ uint32_t s2u(const void* p){
    uint32_t a;
    asm("{ .reg .u64 t; cvta.to.shared.u64 t, %1; cvt.u32.u64 %0, t; }" : "=r"(a) : "l"(p));
    return a;
}
#define LDMX4(r, addr) \
    asm volatile("ldmatrix.sync.aligned.m8n8.x4.shared.b16 {%0,%1,%2,%3}, [%4];" \
        : "=r"((r)[0]), "=r"((r)[1]), "=r"((r)[2]), "=r"((r)[3]) : "r"(addr))
#define MMA16816(c, A, Bv) \
    asm volatile("mma.sync.aligned.m16n8k16.row.col.f32.f16.f16.f32 " \
        "{%0,%1,%2,%3}, {%4,%5,%6,%7}, {%8,%9}, {%0,%1,%2,%3};" \
        : "+f"((c)[0]), "+f"((c)[1]), "+f"((c)[2]), "+f"((c)[3]) \
        : "r"((A)[0]), "r"((A)[1]), "r"((A)[2]), "r"((A)[3]), "r"((Bv)[0]), "r"((Bv)[1]))
#define CPASYNC16(dst, src) \
    asm volatile("cp.async.cg.shared.global [%0], [%1], 16;" :: "r"(dst), "l"(src))
#define PREFETCH_L2(p) \
    asm volatile("prefetch.global.L2 [%0];" :: "l"(p))

__device__ __forceinline__ void grid_barrier(unsigned* ctr, unsigned tgt, int tid){
    __syncthreads();
    if (tid == 0){
        asm volatile("red.release.gpu.global.add.u32 [%0], %1;" :: "l"(ctr), "r"(1u) : "memory");
        unsigned v;
        do {
            asm volatile("ld.acquire.gpu.global.u32 %0, [%1];" : "=r"(v) : "l"(ctr) : "memory");
            if (v < tgt) asm volatile("nanosleep.u32 128;");
        } while (v < tgt);
    }
    __syncthreads();
}

// ------------------------- HMMA GEMM kernel (512 threads) ----------------------
// AT=1: C = (Ah·(Bh+Bl))*INVS + bias
// AT=2: C = (Ah·Bh + Ah·Bl + Al·Bh)*INVS + bias  (head)
struct GArgs {
    const __half *Ahi, *Alo;
    const __half *Bhi, *Blo;
    const float* bias;
    float* C;
    int ldc;
    int K;
};
struct GArgs2 { GArgs a[2]; };

#define RSB   144
#define TILEB (128*RSB)            // 18432
#define STGB  (4*TILEB)            // 73728
#define NSTG  3
#define SMEM_DYN (NSTG*STGB)       // 221184

template<int AT>
__global__ __launch_bounds__(512, 1) void mma_gemm(GArgs2 P)
{
    const GArgs a = P.a[blockIdx.z];
    extern __shared__ char sm[];
    const int tid = threadIdx.x, lane = tid & 31, wid = tid >> 5;
    const int wm = wid & 3, wn = wid >> 2;
    const int m0 = blockIdx.y << 7;
    const int bx = blockIdx.x;
    const int K  = a.K;
    const int KB = K >> 6;

    auto issue = [&](int kb){
        char* sb = sm + (kb % NSTG) * STGB;
        const int k0 = kb << 6;
        const int NI = (AT == 2) ? 8 : 6;
        #pragma unroll
        for (int i = 0; i < NI; i++){
            int tile;
            if (AT == 2) tile = i >> 1;
            else { const int ts = i >> 1; tile = (ts == 0) ? 0 : ts + 1; }
            const int rem  = ((i & 1) << 9) + tid;
            const int row  = rem >> 3;
            const int c8   = rem & 7;
            const __half* src;
            if (tile == 0)      src = a.Ahi + (size_t)(m0 + row) * K + k0 + (c8 << 3);
            else if (tile == 1) src = a.Alo + (size_t)(m0 + row) * K + k0 + (c8 << 3);
            else src = (tile == 2 ? a.Bhi : a.Blo) + (size_t)((bx << 7) + row) * K + k0 + (c8 << 3);
            CPASYNC16(s2u(sb + tile * TILEB + row * RSB + (c8 << 4)), src);
        }
        asm volatile("cp.async.commit_group;" ::: "memory");
    };

    float acc[2][4][4];
    #pragma unroll
    for (int mt = 0; mt < 2; mt++)
        #pragma unroll
        for (int nt = 0; nt < 4; nt++)
            #pragma unroll
            for (int q = 0; q < 4; q++) acc[mt][nt][q] = 0.f;

    issue(0); issue(1);

    for (int kb = 0; kb < KB; kb++){
        if (kb + 2 < KB) issue(kb + 2);
        if (kb == KB - 1)      asm volatile("cp.async.wait_group 0;" ::: "memory");
        else if (kb == KB - 2) asm volatile("cp.async.wait_group 1;" ::: "memory");
        else                   asm volatile("cp.async.wait_group 2;" ::: "memory");
        __syncthreads();

        char* sb = sm + (kb % NSTG) * STGB;
        const uint32_t bAh = s2u(sb);
        const uint32_t bBh = bAh + 2 * TILEB;

        #pragma unroll
        for (int k16 = 0; k16 < 4; k16++){
            uint32_t Ah[2][4], Al[2][4], Bh[4][2], Bl[4][2];
            const int kcbA = (k16 << 5) + (((lane >> 4) & 1) << 4);
            #pragma unroll
            for (int mt = 0; mt < 2; mt++){
                const int row = (wm << 5) + (mt << 4) + (lane & 15);
                const uint32_t ad = bAh + row * RSB + kcbA;
                LDMX4(Ah[mt], ad);
                if (AT == 2) LDMX4(Al[mt], ad + TILEB);
            }
            {
                const int rowb = (wn << 5) + (((lane >> 4) & 1) << 3) + (lane & 7);
                const int kcbB = (k16 << 5) + (((lane >> 3) & 1) << 4);
                const uint32_t bd0 = bBh + rowb * RSB + kcbB;
                const uint32_t bd1 = bd0 + 16 * RSB;
                uint32_t t[4];
                LDMX4(t, bd0); Bh[0][0]=t[0]; Bh[0][1]=t[1]; Bh[1][0]=t[2]; Bh[1][1]=t[3];
                LDMX4(t, bd1); Bh[2][0]=t[0]; Bh[2][1]=t[1]; Bh[3][0]=t[2]; Bh[3][1]=t[3];
                LDMX4(t, bd0 + TILEB); Bl[0][0]=t[0]; Bl[0][1]=t[1]; Bl[1][0]=t[2]; Bl[1][1]=t[3];
                LDMX4(t, bd1 + TILEB); Bl[2][0]=t[0]; Bl[2][1]=t[1]; Bl[3][0]=t[2]; Bl[3][1]=t[3];
            }
            #pragma unroll
            for (int mt = 0; mt < 2; mt++)
                #pragma unroll
                for (int nt = 0; nt < 4; nt++){
                    MMA16816(acc[mt][nt], Ah[mt], Bh[nt]);
                    MMA16816(acc[mt][nt], Ah[mt], Bl[nt]);
                    if (AT == 2) MMA16816(acc[mt][nt], Al[mt], Bh[nt]);
                }
        }
        __syncthreads();
    }

    const int g = lane >> 2, tig = lane & 3;
    #pragma unroll
    for (int mt = 0; mt < 2; mt++){
        const int r = m0 + (wm << 5) + (mt << 4) + g;
        #pragma unroll
        for (int nt = 0; nt < 4; nt++){
            const int n = (bx << 7) + (wn << 5) + (nt << 3) + (tig << 1);
            const float b0 = a.bias[n], b1 = a.bias[n + 1];
            float* c0p = a.C + (size_t)r * a.ldc + n;
            float* c1p = a.C + (size_t)(r + 8) * a.ldc + n;
            c0p[0] = acc[mt][nt][0] * INVS + b0; c0p[1] = acc[mt][nt][1] * INVS + b1;
            c1p[0] = acc[mt][nt][2] * INVS + b0; c1p[1] = acc[mt][nt][3] * INVS + b1;
        }
    }
}

// ==================== persistent fwd+bwd recurrence kernel =====================
// 128 CTAs x 512 threads. Single-term weights resident (73728B), BK=128.
#define FB_WKB  9216
#define FB_ASUB 18432
#define FB_AST  36864
#define FB_ABASE 73728
#define FB_SMEM (FB_ABASE + 2*FB_AST)   // 147456

__global__ __launch_bounds__(512, 1) void lstm_fb()
{
    extern __shared__ char sm[];
    const int tid = threadIdx.x, lane = tid & 31, wid = tid >> 5;
    const int bid = blockIdx.x;
    const int cell = bid & 1, mhalf = (bid >> 1) & 1, jg = bid >> 2;
    const int wm = wid & 3, wn = wid >> 2;

    {   // resident weights: 64 gathered rows x 512 cols, single term
        const __half* Whi = cell ? g_Whhb_hi : g_Whhf_hi;
        #pragma unroll
        for (int i = 0; i < 8; i++){
            const int q = (i << 9) + tid;        // 0..4095
            const int row  = q >> 6;             // 0..63
            const int c    = q & 63;
            const int wrow = (row & 3) * HH + (jg << 4) + (row >> 2);
            const __half* src = Whi + (size_t)wrow * HH + (c << 3);
            CPASYNC16(s2u(sm + (c >> 3) * FB_WKB + row * 144 + ((c & 7) << 4)), src);
        }
        asm volatile("cp.async.commit_group;" ::: "memory");
        asm volatile("cp.async.wait_group 0;" ::: "memory");
        __syncthreads();
    }

    const uint32_t wbase = s2u(sm);
    char* abase = sm + FB_ABASE;
    float* cst = cell ? g_cb : g_cf;
    const int g = lane >> 2, tig = lane & 3;
    const bool odd = (tig & 1);

    for (int s = 0; s < SS; s++){
        const int rb = s & 1, wb = rb ^ 1;
        const __half* Ain = cell ? g_hb[rb] : g_hf[rb];
        const float* Xp = cell ? (g_Xb + (size_t)(SS - 1 - s) * BB * G4H)
                               : (g_Xf + (size_t)s * BB * G4H);

        if (tid < 256){
            const float* pf = Xp + (size_t)((mhalf << 7) + (tid >> 1)) * G4H
                              + ((tid & 1) << 1) * HH + (jg << 4);
            PREFETCH_L2(pf);
            PREFETCH_L2(pf + HH);
        }

        // BK=128: stage holds 2 sub-tiles of 64 cols
        auto issueA = [&](int kb4){
            char* sb = abase + (kb4 & 1) * FB_AST;
            const int k0 = kb4 << 7;
            #pragma unroll
            for (int i = 0; i < 4; i++){
                const int q = (i << 9) + tid;    // 0..2047
                const int sub = q >> 10;
                const int rem = q & 1023;
                const int row = rem >> 3;
                const int c8  = rem & 7;
                const __half* src = Ain + (size_t)((mhalf << 7) + row) * HH
                                    + k0 + (sub << 6) + (c8 << 3);
                CPASYNC16(s2u(sb + sub * FB_ASUB + row * 144 + (c8 << 4)), src);
            }
            asm volatile("cp.async.commit_group;" ::: "memory");
        };

        float acc[2][2][4];
        #pragma unroll
        for (int mt = 0; mt < 2; mt++)
            #pragma unroll
            for (int nt = 0; nt < 2; nt++)
                #pragma unroll
                for (int q = 0; q < 4; q++) acc[mt][nt][q] = 0.f;

        issueA(0);
        for (int kb4 = 0; kb4 < 4; kb4++){
            if (kb4 + 1 < 4){ issueA(kb4 + 1); asm volatile("cp.async.wait_group 1;" ::: "memory"); }
            else             asm volatile("cp.async.wait_group 0;" ::: "memory");
            __syncthreads();
            const uint32_t sa = s2u(abase + (kb4 & 1) * FB_AST);
            #pragma unroll
            for (int k16 = 0; k16 < 8; k16++){
                const int sub = k16 >> 2, kk = k16 & 3;
                uint32_t Ah[2][4], Bh[2][2];
                const int kcbA = (kk << 5) + (((lane >> 4) & 1) << 4);
                #pragma unroll
                for (int mt = 0; mt < 2; mt++){
                    const int row = (wm << 5) + (mt << 4) + (lane & 15);
                    LDMX4(Ah[mt], sa + sub * FB_ASUB + row * 144 + kcbA);
                }
                {
                    const int rowb = (wn << 4) + (((lane >> 4) & 1) << 3) + (lane & 7);
                    const int kcbB = (kk << 5) + (((lane >> 3) & 1) << 4);
                    const uint32_t bw = wbase + ((kb4 << 1) + sub) * FB_WKB + rowb * 144 + kcbB;
                    uint32_t t[4];
                    LDMX4(t, bw); Bh[0][0]=t[0]; Bh[0][1]=t[1]; Bh[1][0]=t[2]; Bh[1][1]=t[3];
                }
                #pragma unroll
                for (int mt = 0; mt < 2; mt++)
                    #pragma unroll
                    for (int nt = 0; nt < 2; nt++)
                        MMA16816(acc[mt][nt], Ah[mt], Bh[nt]);
            }
            __syncthreads();
        }

        __half* Hout = cell ? g_hb[wb] : g_hf[wb];
        #pragma unroll
        for (int mt = 0; mt < 2; mt++)
            #pragma unroll
            for (int nt = 0; nt < 2; nt++){
                float c0 = acc[mt][nt][0], c1 = acc[mt][nt][1];
                float c2 = acc[mt][nt][2], c3 = acc[mt][nt][3];
                float e0 = __shfl_xor_sync(0xFFFFFFFFu, odd ? c0 : c2, 1);
                float e1 = __shfl_xor_sync(0xFFFFFFFFu, odd ? c1 : c3, 1);
                const int r = (mhalf << 7) + (wm << 5) + (mt << 4) + g + (odd ? 8 : 0);
                const int j = (jg << 4) + (wn << 2) + (nt << 1) + (tig >> 1);
                float gi, gf, gg, go;
                if (odd){ gi = e0; gf = e1; gg = c2; go = c3; }
                else    { gi = c0; gf = c1; gg = e0; go = e1; }
                const float* Xrow = Xp + (size_t)r * G4H;
                gi = gi * INVS + Xrow[j];
                gf = gf * INVS + Xrow[HH + j];
                gg = gg * INVS + Xrow[2*HH + j];
                go = go * INVS + Xrow[3*HH + j];
                const float ii = 1.f / (1.f + expf(-gi));
                const float ff = 1.f / (1.f + expf(-gf));
                const float gt = tanhf(gg);
                const float oo = 1.f / (1.f + expf(-go));
                const size_t si = (size_t)r * HH + j;
                const float cn = ff * cst[si] + ii * gt;
                const float hn = oo * tanhf(cn);
                cst[si] = cn;
                const __half hh = __float2half(hn);
                Hout[si] = hh;
                g_comb[(size_t)(s * BB + r) * H2 + cell * HH + j] = hh;
            }

        grid_barrier(&g_ctr_fb, 128u * (unsigned)(s + 1), tid);
    }
}

// ==================== persistent combiner recurrence kernel ====================
// 128 CTAs x 512 threads. Single-term weights (65536B), BK=128 (4 sub-chunks).
#define CW_KB   2048
#define CA_BASE 65536
#define CA_SUB  16384
#define CA_ST   65536
#define COMB_SMEM (CA_BASE + 2*CA_ST)   // 196608

__device__ __forceinline__ uint32_t csw(int row, int c){
    return (uint32_t)(row * 64 + ((c ^ ((row >> 1) & 3)) << 4));
}

__global__ __launch_bounds__(512, 1) void lstm_comb()
{
    extern __shared__ char sm[];
    const int tid = threadIdx.x, lane = tid & 31, wid = tid >> 5;
    const int jg = blockIdx.x;
    const int wm = wid & 7, wn = wid >> 3;

    {   // resident weights: 32 gathered rows x 1024 cols, single term
        #pragma unroll
        for (int i = 0; i < 8; i++){
            const int q = (i << 9) + tid;        // 0..4095
            const int row  = q >> 7;             // 0..31
            const int cc   = q & 127;
            const int kb   = cc >> 2;
            const int c    = cc & 3;
            const int wrow = (row & 3) * H2 + (jg << 3) + (row >> 2);
            const __half* src = g_Whhc_hi + (size_t)wrow * H2 + (cc << 3);
            CPASYNC16(s2u(sm + kb * CW_KB + csw(row, c)), src);
        }
        asm volatile("cp.async.commit_group;" ::: "memory");
        asm volatile("cp.async.wait_group 0;" ::: "memory");
        __syncthreads();
    }

    const uint32_t wbase = s2u(sm);
    char* abase = sm + CA_BASE;
    const int g = lane >> 2, tig = lane & 3;
    const bool odd = (tig & 1);

    for (int s = 0; s < SS; s++){
        const int rb = s & 1, wb = rb ^ 1;
        const __half* Ain = g_hc_hi[rb];
        const float* Xp = g_Xc + (size_t)s * BB * G8H;

        if (tid < 256){
            const float* pf = Xp + (size_t)tid * G8H + (jg << 3);
            PREFETCH_L2(pf);
            PREFETCH_L2(pf + H2);
            PREFETCH_L2(pf + 2 * H2);
            PREFETCH_L2(pf + 3 * H2);
        }

        // BK=128: stage = 4 sub-chunks of 32 cols
        auto issueA = [&](int kb4){
            char* sb = abase + (kb4 & 1) * CA_ST;
            const int k0 = kb4 << 7;
            #pragma unroll
            for (int i = 0; i < 8; i++){
                const int q = (i << 9) + tid;    // 0..4095
                const int sub = q >> 10;
                const int rem = q & 1023;
                const int row = rem >> 2;
                const int c   = rem & 3;
                const __half* src = Ain + (size_t)row * H2 + k0 + (sub << 5) + (c << 3);
                CPASYNC16(s2u(sb + sub * CA_SUB + csw(row, c)), src);
            }
            asm volatile("cp.async.commit_group;" ::: "memory");
        };

        float acc[2][2][4];
        #pragma unroll
        for (int mt = 0; mt < 2; mt++)
            #pragma unroll
            for (int nt = 0; nt < 2; nt++)
                #pragma unroll
                for (int q = 0; q < 4; q++) acc[mt][nt][q] = 0.f;

        issueA(0);
        for (int kb4 = 0; kb4 < 8; kb4++){
            if (kb4 + 1 < 8){ issueA(kb4 + 1); asm volatile("cp.async.wait_group 1;" ::: "memory"); }
            else             asm volatile("cp.async.wait_group 0;" ::: "memory");
            __syncthreads();
            const uint32_t sa = s2u(abase + (kb4 & 1) * CA_ST);
            #pragma unroll
            for (int k16 = 0; k16 < 8; k16++){
                const int sub = k16 >> 1, kk = k16 & 1;
                uint32_t Ah[2][4], Bh[2][2];
                const int cA = (kk << 1) + ((lane >> 4) & 1);
                #pragma unroll
                for (int mt = 0; mt < 2; mt++){
                    const int row = (wm << 5) + (mt << 4) + (lane & 15);
                    LDMX4(Ah[mt], sa + sub * CA_SUB + csw(row, cA));
                }
                {
                    const int rowb = (wn << 4) + (((lane >> 4) & 1) << 3) + (lane & 7);
                    const int cB = (kk << 1) + ((lane >> 3) & 1);
                    const uint32_t bw = wbase + ((kb4 << 2) + sub) * CW_KB + csw(rowb, cB);
                    uint32_t t[4];
                    LDMX4(t, bw); Bh[0][0]=t[0]; Bh[0][1]=t[1]; Bh[1][0]=t[2]; Bh[1][1]=t[3];
                }
                #pragma unroll
                for (int mt = 0; mt < 2; mt++)
                    #pragma unroll
                    for (int nt = 0; nt < 2; nt++)
                        MMA16816(acc[mt][nt], Ah[mt], Bh[nt]);
            }
            __syncthreads();
        }

        #pragma unroll
        for (int mt = 0; mt < 2; mt++)
            #pragma unroll
            for (int nt = 0; nt < 2; nt++){
                float c0 = acc[mt][nt][0], c1 = acc[mt][nt][1];
                float c2 = acc[mt][nt][2], c3 = acc[mt][nt][3];
                float e0 = __shfl_xor_sync(0xFFFFFFFFu, odd ? c0 : c2, 1);
                float e1 = __shfl_xor_sync(0xFFFFFFFFu, odd ? c1 : c3, 1);
                const int r = (wm << 5) + (mt << 4) + g + (odd ? 8 : 0);
                const int j = (jg << 3) + (wn << 2) + (nt << 1) + (tig >> 1);
                float gi, gf, gg, go;
                if (odd){ gi = e0; gf = e1; gg = c2; go = c3; }
                else    { gi = c0; gf = c1; gg = e0; go = e1; }
                const float* Xrow = Xp + (size_t)r * G8H;
                gi = gi * INVS + Xrow[j];
                gf = gf * INVS + Xrow[H2 + j];
                gg = gg * INVS + Xrow[2*H2 + j];
                go = go * INVS + Xrow[3*H2 + j];
                const float ii = 1.f / (1.f + expf(-gi));
                const float ff = 1.f / (1.f + expf(-gf));
                const float gt = tanhf(gg);
                const float oo = 1.f / (1.f + expf(-go));
                const size_t si = (size_t)r * H2 + j;
                const float cn = ff * g_cc[si] + ii * gt;
                const float hn = oo * tanhf(cn);
                g_cc[si] = cn;
                const __half hh = __float2half(hn);
                g_hc_hi[wb][si] = hh;
                g_hc_lo[wb][si] = __float2half(hn - __half2float(hh));
            }

        grid_barrier(&g_ctr_c, 128u * (unsigned)(s + 1), tid);
    }
}

// ------------------------- fused prep kernel -----------------------------------
__device__ __forceinline__ void splitw(const float* __restrict__ src,
                                       __half* __restrict__ hi,
                                       __half* __restrict__ lo, long i){
    float v = src[i] * WSCALE;
    __half h = __float2half(v);
    hi[i] = h;
    if (lo) lo[i] = __float2half(v - __half2float(h));
}

#define SZ_FB  (G4H*HH)
#define SZ_C   (G8H*H2)
#define SZ_OUT ((long)VV*H2)
#define OFF_SPLITS (4L*SZ_FB + 2L*SZ_C + SZ_OUT)
#define OFF_EMB    (OFF_SPLITS + (long)SB*HH)
#define OFF_ST1    (OFF_EMB + (long)BB*HH)
#define OFF_ST2    (OFF_ST1 + (long)BB*H2)
#define OFF_END    (OFF_ST2 + G4H + G4H + G8H)

__global__ void prep_all(const int* __restrict__ x, const float* __restrict__ Wemb,
                         const float* Wih_f, const float* Whh_f, const float* bih_f, const float* bhh_f,
                         const float* Wih_b, const float* Whh_b, const float* bih_b, const float* bhh_b,
                         const float* Wih_c, const float* Whh_c, const float* bih_c, const float* bhh_c,
                         const float* Wout,
                         const float* h0f, const float* c0f, const float* h0b, const float* c0b,
                         const float* h0c, const float* c0c)
{
    const long stride = (long)gridDim.x * blockDim.x;
    for (long i = (long)blockIdx.x * blockDim.x + threadIdx.x; i < OFF_END; i += stride){
        if (i == 0){ g_ctr_fb = 0; g_ctr_c = 0; }
        if (i < OFF_SPLITS){
            long r = i;
            if (r < SZ_FB){ splitw(Wih_f, g_Wihf_hi, g_Wihf_lo, r); continue; } r -= SZ_FB;
            if (r < SZ_FB){ splitw(Whh_f, g_Whhf_hi, nullptr, r); continue; } r -= SZ_FB;
            if (r < SZ_FB){ splitw(Wih_b, g_Wihb_hi, g_Wihb_lo, r); continue; } r -= SZ_FB;
            if (r < SZ_FB){ splitw(Whh_b, g_Whhb_hi, nullptr, r); continue; } r -= SZ_FB;
            if (r < SZ_C){ splitw(Wih_c, g_Wihc_hi, g_Wihc_lo, r); continue; } r -= SZ_C;
            if (r < SZ_C){ splitw(Whh_c, g_Whhc_hi, nullptr, r); continue; } r -= SZ_C;
            splitw(Wout, g_Wout_hi, g_Wout_lo, r);
        } else if (i < OFF_EMB){
            long e = i - OFF_SPLITS;
            int row = (int)(e >> 9), k = (int)(e & 511);
            int tok = x[row];
            float v = tok ? Wemb[(size_t)tok * HH + k] : 0.f;
            g_seq[e] = __float2half(v);
        } else if (i < OFF_ST1){
            long t = i - OFF_EMB;
            g_hf[0][t] = __float2half(h0f[t]); g_cf[t] = c0f[t];
            g_hb[0][t] = __float2half(h0b[t]); g_cb[t] = c0b[t];
        } else if (i < OFF_ST2){
            long t = i - OFF_ST1;
            float vc = h0c[t];
            __half hh = __float2half(vc);
            g_hc_hi[0][t] = hh;
            g_hc_lo[0][t] = __float2half(vc - __half2float(hh));
            g_cc[t] = c0c[t];
        } else {
            long b = i - OFF_ST2;
            if (b < G4H) g_bfb[b] = bih_f[b] + bhh_f[b];
            else if (b < 2*G4H) g_bbb[b - G4H] = bih_b[b - G4H] + bhh_b[b - G4H];
            else g_bcb[b - 2*G4H] = bih_c[b - 2*G4H] + bhh_c[b - 2*G4H];
        }
    }
}

// ------------------------- host orchestration ---------------------------------
static void* sym(const void* s){ void* p; cudaGetSymbolAddress(&p, s); return p; }

extern "C" void kernel_launch(void* const* d_in, const int* in_sizes, int n_in,
                              void* d_out, int out_size) {
    (void)in_sizes; (void)n_in; (void)out_size;

    const int*   x     = (const int*)  d_in[0];
    const float* Wemb  = (const float*)d_in[1];
    const float* Wih_f = (const float*)d_in[2];
    const float* Whh_f = (const float*)d_in[3];
    const float* bih_f = (const float*)d_in[4];
    const float* bhh_f = (const float*)d_in[5];
    const float* Wih_b = (const float*)d_in[6];
    const float* Whh_b = (const float*)d_in[7];
    const float* bih_b = (const float*)d_in[8];
    const float* bhh_b = (const float*)d_in[9];
    const float* Wih_c = (const float*)d_in[10];
    const float* Whh_c = (const float*)d_in[11];
    const float* bih_c = (const float*)d_in[12];
    const float* bhh_c = (const float*)d_in[13];
    const float* Wout  = (const float*)d_in[14];
    const float* bout  = (const float*)d_in[15];
    const float* h0f   = (const float*)d_in[16];
    const float* c0f   = (const float*)d_in[17];
    const float* h0b   = (const float*)d_in[18];
    const float* c0b   = (const float*)d_in[19];
    const float* h0c   = (const float*)d_in[20];
    const float* c0c   = (const float*)d_in[21];
    float* out = (float*)d_out;

    cudaFuncSetAttribute(mma_gemm<1>, cudaFuncAttributeMaxDynamicSharedMemorySize, SMEM_DYN);
    cudaFuncSetAttribute(mma_gemm<2>, cudaFuncAttributeMaxDynamicSharedMemorySize, SMEM_DYN);
    cudaFuncSetAttribute(lstm_fb,     cudaFuncAttributeMaxDynamicSharedMemorySize, FB_SMEM);
    cudaFuncSetAttribute(lstm_comb,   cudaFuncAttributeMaxDynamicSharedMemorySize, COMB_SMEM);

    __half *seq = (__half*)sym(g_seq), *cmb = (__half*)sym(g_comb);
    float *Xf = (float*)sym(g_Xf), *Xb = (float*)sym(g_Xb), *Xc = (float*)sym(g_Xc);
    __half *Wihf_hi=(__half*)sym(g_Wihf_hi), *Wihf_lo=(__half*)sym(g_Wihf_lo);
    __half *Wihb_hi=(__half*)sym(g_Wihb_hi), *Wihb_lo=(__half*)sym(g_Wihb_lo);
    __half *Wihc_hi=(__half*)sym(g_Wihc_hi), *Wihc_lo=(__half*)sym(g_Wihc_lo);
    __half *Wout_hi=(__half*)sym(g_Wout_hi), *Wout_lo=(__half*)sym(g_Wout_lo);
    float *bfb=(float*)sym(g_bfb), *bbb=(float*)sym(g_bbb), *bcb=(float*)sym(g_bcb);
    __half *hc_hi=(__half*)sym(g_hc_hi), *hc_lo=(__half*)sym(g_hc_lo);

    // launch 0: fused prep
    prep_all<<<4096, 256>>>(x, Wemb,
                            Wih_f, Whh_f, bih_f, bhh_f,
                            Wih_b, Whh_b, bih_b, bhh_b,
                            Wih_c, Whh_c, bih_c, bhh_c,
                            Wout, h0f, c0f, h0b, c0b, h0c, c0c);

    GArgs2 P; GArgs z; memset(&z, 0, sizeof(z));

    // launch 1: Xf + Xb (AT=1)
    P.a[0]=z; P.a[0].Ahi=seq; P.a[0].Alo=seq; P.a[0].Bhi=Wihf_hi; P.a[0].Blo=Wihf_lo;
    P.a[0].bias=bfb; P.a[0].C=Xf; P.a[0].ldc=G4H; P.a[0].K=HH;
    P.a[1]=P.a[0]; P.a[1].Bhi=Wihb_hi; P.a[1].Blo=Wihb_lo; P.a[1].bias=bbb; P.a[1].C=Xb;
    mma_gemm<1><<<dim3(G4H/128, SB/128, 2), 512, SMEM_DYN>>>(P);

    // launch 2: persistent fwd+bwd recurrence (single-term weights, BK=128)
    lstm_fb<<<128, 512, FB_SMEM>>>();

    // launch 3: Xc (AT=1)
    P.a[0]=z; P.a[0].Ahi=cmb; P.a[0].Alo=cmb; P.a[0].Bhi=Wihc_hi; P.a[0].Blo=Wihc_lo;
    P.a[0].bias=bcb; P.a[0].C=Xc; P.a[0].ldc=G8H; P.a[0].K=H2; P.a[1]=P.a[0];
    mma_gemm<1><<<dim3(G8H/128, SB/128, 1), 512, SMEM_DYN>>>(P);

    // launch 4: persistent combiner recurrence (single-term weights, BK=128)
    lstm_comb<<<128, 512, COMB_SMEM>>>();

    // launch 5: head (AT=2)
    P.a[0]=z; P.a[0].Ahi=hc_hi; P.a[0].Alo=hc_lo; P.a[0].Bhi=Wout_hi; P.a[0].Blo=Wout_lo;
    P.a[0].bias=bout; P.a[0].C=out; P.a[0].ldc=VV; P.a[0].K=H2; P.a[1]=P.a[0];
    mma_gemm<2><<<dim3(VV/128, BB/128, 1), 512, SMEM_DYN>>>(P);
}